// round 1
// baseline (speedup 1.0000x reference)
#include <cuda_runtime.h>
#include <cuda_fp16.h>
#include <cuda_bf16.h>

// Problem constants
#define BB 64
#define TT 512
#define EE 768
#define HH 128      // hidden per direction
#define G4 512      // 4*H
#define KK 11

// ---------------------------------------------------------------------------
// Scratch (device globals; no dynamic allocation allowed)
// ---------------------------------------------------------------------------
__device__ float g_XP[(size_t)TT * BB * 1024];   // gate x-contributions, [t][b][dir*512+g]
__device__ float g_H0[(size_t)TT * BB * 256];    // layer0 output  [t][b][dir*128+h]
__device__ float g_H1[(size_t)TT * BB * 256];    // layer1 output
__device__ float g_EM[(size_t)TT * BB * 16];     // emissions padded to 16
__device__ float g_ND[BB];                       // num - den per batch

__device__ __forceinline__ float sigf(float x) { return 1.f / (1.f + __expf(-x)); }

__device__ __forceinline__ __half2 u2h2(unsigned int u) {
    __half2 r; *reinterpret_cast<unsigned int*>(&r) = u; return r;
}
__device__ __forceinline__ unsigned int packh2(float a, float b) {
    __half2 h = __floats2half2_rn(a, b);
    return *reinterpret_cast<unsigned int*>(&h);
}

// ---------------------------------------------------------------------------
// GEMM: XP[r][n] = A[r][:] . W[n][:] + (b_ih[n]+b_hh[n]),  r = t*64+b
// amode 0: A = embeds (B,T,E): row r -> offset ((r&63)*512 + (r>>6))*768
// amode 1: A = g_H0 (T,B,256): row r -> offset r*256
// n < 512 -> (W0, bi0+bh0) fwd, else (W1, bi1+bh1) bwd
// Tile: BM=128, BN=64, BK=8, per-thread 8x4, 256 threads.
// ---------------------------------------------------------------------------
__global__ __launch_bounds__(256) void gemm_xproj(
    const float* __restrict__ Aext, int amode, int Kdim,
    const float* __restrict__ W0, const float* __restrict__ W1,
    const float* __restrict__ bi0, const float* __restrict__ bh0,
    const float* __restrict__ bi1, const float* __restrict__ bh1)
{
    __shared__ float As[8][128];
    __shared__ float Bs[8][64];

    const float* A = (amode == 0) ? Aext : g_H0;

    const int tid = threadIdx.x;
    const int tx = tid & 15;      // 0..15 (n-sub)
    const int ty = tid >> 4;      // 0..15 (m-sub)
    const int row0 = blockIdx.y * 128;
    const int col0 = blockIdx.x * 64;

    // A tile load mapping: 128x8 floats, float4 per thread
    const int lam = tid >> 1;           // 0..127
    const int lak = (tid & 1) * 4;      // 0 or 4
    size_t aoff;
    {
        int r = row0 + lam;
        if (amode == 0) aoff = ((size_t)(r & 63) * 512 + (size_t)(r >> 6)) * 768;
        else            aoff = (size_t)r * (size_t)Kdim;
    }

    // B tile load mapping: 64x8 floats, float2 per thread
    const int lbn = tid >> 2;           // 0..63
    const int lbk = (tid & 3) * 2;      // 0,2,4,6
    const int nG  = col0 + lbn;
    const float* wrow = (nG < 512) ? (W0 + (size_t)nG * Kdim)
                                   : (W1 + (size_t)(nG - 512) * Kdim);

    float acc[8][4];
#pragma unroll
    for (int i = 0; i < 8; i++)
#pragma unroll
        for (int j = 0; j < 4; j++) acc[i][j] = 0.f;

    for (int k0 = 0; k0 < Kdim; k0 += 8) {
        float4 av = *reinterpret_cast<const float4*>(A + aoff + k0 + lak);
        float2 bv = *reinterpret_cast<const float2*>(wrow + k0 + lbk);
        As[lak + 0][lam] = av.x;
        As[lak + 1][lam] = av.y;
        As[lak + 2][lam] = av.z;
        As[lak + 3][lam] = av.w;
        Bs[lbk + 0][lbn] = bv.x;
        Bs[lbk + 1][lbn] = bv.y;
        __syncthreads();

#pragma unroll
        for (int kk = 0; kk < 8; kk++) {
            float ra[8], rb[4];
#pragma unroll
            for (int i = 0; i < 8; i++) ra[i] = As[kk][ty * 8 + i];
#pragma unroll
            for (int j = 0; j < 4; j++) rb[j] = Bs[kk][tx * 4 + j];
#pragma unroll
            for (int i = 0; i < 8; i++)
#pragma unroll
                for (int j = 0; j < 4; j++) acc[i][j] += ra[i] * rb[j];
        }
        __syncthreads();
    }

    // bias per output column (fixed per thread)
    const int n0 = col0 + tx * 4;
    float bias[4];
#pragma unroll
    for (int j = 0; j < 4; j++) {
        int n = n0 + j;
        bias[j] = (n < 512) ? (bi0[n] + bh0[n]) : (bi1[n - 512] + bh1[n - 512]);
    }

#pragma unroll
    for (int i = 0; i < 8; i++) {
        int r = row0 + ty * 8 + i;
        float4 o;
        o.x = acc[i][0] + bias[0];
        o.y = acc[i][1] + bias[1];
        o.z = acc[i][2] + bias[2];
        o.w = acc[i][3] + bias[3];
        *reinterpret_cast<float4*>(&g_XP[(size_t)r * 1024 + n0]) = o;
    }
}

// ---------------------------------------------------------------------------
// LSTM recurrence: one block per (batch, dir). 512 threads, thread g = gate g.
// Whh in SMEM as fp16 (k8-major uint4 layout: W4[k8][g] = 8 halves W[g][8k8..]).
// Dynamic smem: 128KB weights + gates(2KB) + c(512B) + h(256B half)
// ---------------------------------------------------------------------------
#define LSTM_SMEM (16 * 512 * 16 + 512 * 4 + 128 * 4 + 128 * 2)

__global__ __launch_bounds__(512) void lstm_kernel(
    const float* __restrict__ whh_fwd, const float* __restrict__ whh_rev, int layer)
{
    extern __shared__ char smem[];
    uint4* W4     = reinterpret_cast<uint4*>(smem);                 // [16][512]
    float* gates  = reinterpret_cast<float*>(smem + 16 * 512 * 16); // 512
    float* cst    = gates + 512;                                    // 128
    __half* hh    = reinterpret_cast<__half*>(cst + 128);           // 128

    float* Hout = layer ? g_H1 : g_H0;
    const int b   = blockIdx.x >> 1;
    const int dir = blockIdx.x & 1;
    const float* whh = dir ? whh_rev : whh_fwd;
    const int g = threadIdx.x;

    // load + convert weights: thread g owns row g
    {
        const float4* wrow = reinterpret_cast<const float4*>(whh + (size_t)g * 128);
#pragma unroll
        for (int k8 = 0; k8 < 16; ++k8) {
            float4 f0 = wrow[k8 * 2];
            float4 f1 = wrow[k8 * 2 + 1];
            uint4 u;
            u.x = packh2(f0.x, f0.y);
            u.y = packh2(f0.z, f0.w);
            u.z = packh2(f1.x, f1.y);
            u.w = packh2(f1.z, f1.w);
            W4[k8 * 512 + g] = u;
        }
    }
    if (g < 128) { cst[g] = 0.f; hh[g] = __float2half_rn(0.f); }
    __syncthreads();

    const uint4* h4 = reinterpret_cast<const uint4*>(hh);   // 16 uint4

    for (int t = 0; t < TT; ++t) {
        const int tt = dir ? (TT - 1 - t) : t;
        const float xpv = g_XP[((size_t)tt * BB + b) * 1024 + dir * 512 + g];

        float accf = 0.f;
#pragma unroll
        for (int k8 = 0; k8 < 16; k8 += 2) {
            uint4 wa = W4[k8 * 512 + g];
            uint4 wb = W4[(k8 + 1) * 512 + g];
            uint4 ha = h4[k8];
            uint4 hb = h4[k8 + 1];
            __half2 a = __float2half2_rn(0.f);
            a = __hfma2(u2h2(wa.x), u2h2(ha.x), a);
            a = __hfma2(u2h2(wa.y), u2h2(ha.y), a);
            a = __hfma2(u2h2(wa.z), u2h2(ha.z), a);
            a = __hfma2(u2h2(wa.w), u2h2(ha.w), a);
            a = __hfma2(u2h2(wb.x), u2h2(hb.x), a);
            a = __hfma2(u2h2(wb.y), u2h2(hb.y), a);
            a = __hfma2(u2h2(wb.z), u2h2(hb.z), a);
            a = __hfma2(u2h2(wb.w), u2h2(hb.w), a);
            float2 f2 = __half22float2(a);
            accf += f2.x + f2.y;
        }
        gates[g] = accf + xpv;
        __syncthreads();

        if (g < 128) {
            float iv = gates[g];
            float fv = gates[128 + g];
            float gv = gates[256 + g];
            float ov = gates[384 + g];
            float cn = sigf(fv) * cst[g] + sigf(iv) * tanhf(gv);
            float hn = sigf(ov) * tanhf(cn);
            cst[g] = cn;
            hh[g] = __float2half_rn(hn);
            Hout[((size_t)tt * BB + b) * 256 + dir * 128 + g] = hn;
        }
        __syncthreads();
    }
}

// ---------------------------------------------------------------------------
// Emissions: EM[r][n] = H1[r][:] . linear_w[n][:] + linear_b[n], n padded to 16
// ---------------------------------------------------------------------------
__global__ __launch_bounds__(256) void emis_kernel(
    const float* __restrict__ lw, const float* __restrict__ lb)
{
    const int r = blockIdx.x * 16 + (threadIdx.x >> 4);
    const int n = threadIdx.x & 15;
    float acc = 0.f;
    if (n < KK) {
        const float4* h4 = reinterpret_cast<const float4*>(&g_H1[(size_t)r * 256]);
        const float4* w4 = reinterpret_cast<const float4*>(lw + (size_t)n * 256);
#pragma unroll 8
        for (int k = 0; k < 64; ++k) {
            float4 a = h4[k], w = w4[k];
            acc += a.x * w.x + a.y * w.y + a.z * w.z + a.w * w.w;
        }
        acc += lb[n];
    }
    g_EM[(size_t)r * 16 + n] = acc;
}

// ---------------------------------------------------------------------------
// CRF: one block per batch. Numerator (parallel over t) + denominator
// (forward algorithm, warp 0, lanes 0..10 own states).
// ---------------------------------------------------------------------------
__global__ __launch_bounds__(256) void crf_kernel(
    const int* __restrict__ tags, const void* __restrict__ maskraw,
    const float* __restrict__ start_t, const float* __restrict__ end_t,
    const float* __restrict__ trans)
{
    __shared__ float ems[TT * 12];
    __shared__ float redf[256];
    __shared__ int   redi[256];
    __shared__ unsigned char maskb[TT];
    __shared__ float s_num;

    const int b = blockIdx.x;
    const int tid = threadIdx.x;

    // mask layout detection: byte[1]!=0 -> 1-byte elements; else 4-byte (int32/f32(1.0))
    {
        const unsigned char* mc = reinterpret_cast<const unsigned char*>(maskraw);
        const bool bytewise = (mc[1] != 0);
        const int* mi = reinterpret_cast<const int*>(maskraw);
        for (int t = tid; t < TT; t += 256) {
            maskb[t] = bytewise ? (mc[(size_t)b * TT + t] != 0)
                                : (mi[(size_t)b * TT + t] != 0);
        }
    }
    // stage emissions for this batch
    for (int base = tid; base < TT * 16; base += 256) {
        int t = base >> 4, j = base & 15;
        if (j < KK) ems[t * 12 + j] = g_EM[((size_t)t * BB + b) * 16 + j];
    }
    __syncthreads();

    // ---- numerator (parallel over t) ----
    float part = 0.f;
    int   cnt  = 0;
    for (int t = tid; t < TT; t += 256) cnt += maskb[t] ? 1 : 0;
    for (int t = 1 + tid; t < TT; t += 256) {
        if (maskb[t]) {
            int tp = tags[(size_t)b * TT + t - 1];
            int tc = tags[(size_t)b * TT + t];
            part += trans[tp * KK + tc] + ems[t * 12 + tc];
        }
    }
    redf[tid] = part; redi[tid] = cnt;
    __syncthreads();
    for (int s = 128; s > 0; s >>= 1) {
        if (tid < s) { redf[tid] += redf[tid + s]; redi[tid] += redi[tid + s]; }
        __syncthreads();
    }
    if (tid == 0) {
        int t0 = tags[(size_t)b * TT];
        int seqEnd = redi[0] - 1;
        float num = start_t[t0] + ems[t0] + redf[0]
                  + end_t[tags[(size_t)b * TT + seqEnd]];
        s_num = num;
    }
    __syncthreads();

    // ---- denominator (warp 0) ----
    if (tid < 32) {
        const int lane = tid;
        float tcol[KK];
        if (lane < KK) {
#pragma unroll
            for (int i = 0; i < KK; i++) tcol[i] = trans[i * KK + lane];
        } else {
#pragma unroll
            for (int i = 0; i < KK; i++) tcol[i] = 0.f;
        }
        float score = (lane < KK) ? (start_t[lane] + ems[lane]) : -1e30f;

        for (int t = 1; t < TT; ++t) {
            if (maskb[t]) {
                float vi[KK];
                float m = -1e30f;
#pragma unroll
                for (int i = 0; i < KK; i++) {
                    float si = __shfl_sync(0xffffffffu, score, i);
                    vi[i] = si + tcol[i];
                    m = fmaxf(m, vi[i]);
                }
                float ssum = 0.f;
#pragma unroll
                for (int i = 0; i < KK; i++) ssum += __expf(vi[i] - m);
                float nxt = m + __logf(ssum) + ems[t * 12 + lane];
                if (lane < KK) score = nxt;
            }
        }
        float v = (lane < KK) ? (score + end_t[lane]) : -1e30f;
        float m = v;
#pragma unroll
        for (int off = 16; off > 0; off >>= 1)
            m = fmaxf(m, __shfl_xor_sync(0xffffffffu, m, off));
        float e = __expf(v - m);
#pragma unroll
        for (int off = 16; off > 0; off >>= 1)
            e += __shfl_xor_sync(0xffffffffu, e, off);
        float den = m + __logf(e);
        if (lane == 0) g_ND[b] = s_num - den;
    }
}

__global__ void finish_kernel(float* __restrict__ out, int out_n)
{
    __shared__ float s[64];
    int tid = threadIdx.x;
    s[tid] = g_ND[tid];
    __syncthreads();
    for (int st = 32; st > 0; st >>= 1) {
        if (tid < st) s[tid] += s[tid + st];
        __syncthreads();
    }
    if (tid == 0) out[0] = -s[0] / 64.f;
    if (tid > 0 && tid < out_n) out[tid] = 0.f;
}

// ---------------------------------------------------------------------------
extern "C" void kernel_launch(void* const* d_in, const int* in_sizes, int n_in,
                              void* d_out, int out_size)
{
    const float* embeds    = (const float*)d_in[0];
    const int*   tags      = (const int*)d_in[1];
    const void*  mask      = d_in[2];
    const float* w_ih_l0   = (const float*)d_in[3];
    const float* w_hh_l0   = (const float*)d_in[4];
    const float* b_ih_l0   = (const float*)d_in[5];
    const float* b_hh_l0   = (const float*)d_in[6];
    const float* w_ih_l0r  = (const float*)d_in[7];
    const float* w_hh_l0r  = (const float*)d_in[8];
    const float* b_ih_l0r  = (const float*)d_in[9];
    const float* b_hh_l0r  = (const float*)d_in[10];
    const float* w_ih_l1   = (const float*)d_in[11];
    const float* w_hh_l1   = (const float*)d_in[12];
    const float* b_ih_l1   = (const float*)d_in[13];
    const float* b_hh_l1   = (const float*)d_in[14];
    const float* w_ih_l1r  = (const float*)d_in[15];
    const float* w_hh_l1r  = (const float*)d_in[16];
    const float* b_ih_l1r  = (const float*)d_in[17];
    const float* b_hh_l1r  = (const float*)d_in[18];
    const float* linear_w  = (const float*)d_in[19];
    const float* linear_b  = (const float*)d_in[20];
    const float* start_tr  = (const float*)d_in[21];
    const float* end_tr    = (const float*)d_in[22];
    const float* trans     = (const float*)d_in[23];
    (void)in_sizes; (void)n_in;

    cudaFuncSetAttribute(lstm_kernel, cudaFuncAttributeMaxDynamicSharedMemorySize,
                         LSTM_SMEM);

    dim3 ggrid(16, 256);  // N/64 x M/128

    // layer 0
    gemm_xproj<<<ggrid, 256>>>(embeds, 0, 768,
                               w_ih_l0, w_ih_l0r, b_ih_l0, b_hh_l0, b_ih_l0r, b_hh_l0r);
    lstm_kernel<<<128, 512, LSTM_SMEM>>>(w_hh_l0, w_hh_l0r, 0);

    // layer 1 (reuses g_XP; reads g_H0 internally)
    gemm_xproj<<<ggrid, 256>>>(embeds, 1, 256,
                               w_ih_l1, w_ih_l1r, b_ih_l1, b_hh_l1, b_ih_l1r, b_hh_l1r);
    lstm_kernel<<<128, 512, LSTM_SMEM>>>(w_hh_l1, w_hh_l1r, 1);

    // emissions + CRF
    emis_kernel<<<2048, 256>>>(linear_w, linear_b);
    crf_kernel<<<64, 256>>>(tags, mask, start_tr, end_tr, trans);
    finish_kernel<<<1, 64>>>((float*)d_out, out_size);
}

// round 2
// speedup vs baseline: 1.9657x; 1.9657x over previous
#include <cuda_runtime.h>
#include <cuda_fp16.h>
#include <cuda_bf16.h>

// Problem constants
#define BB 64
#define TT 512
#define EE 768
#define HH 128      // hidden per direction
#define KK 11

// ---------------------------------------------------------------------------
// Scratch (device globals; no dynamic allocation allowed)
// ---------------------------------------------------------------------------
__device__ float g_XP[(size_t)TT * BB * 1024];   // gate x-contributions, [t][b][dir*512+g]
__device__ float g_H0[(size_t)TT * BB * 256];    // layer0 output  [t][b][dir*128+h]
__device__ float g_H1[(size_t)TT * BB * 256];    // layer1 output
__device__ float g_EM[(size_t)TT * BB * 16];     // emissions padded to 16
__device__ float g_ND[BB];                       // num - den per batch

__device__ __forceinline__ float sigf(float x) { return 1.f / (1.f + __expf(-x)); }
__device__ __forceinline__ float tanhfast(float x) { return 2.f * sigf(2.f * x) - 1.f; }

__device__ __forceinline__ __half2 u2h2(unsigned int u) {
    __half2 r; *reinterpret_cast<unsigned int*>(&r) = u; return r;
}
__device__ __forceinline__ unsigned f2tf32(float x) {
    unsigned u; asm("cvt.rna.tf32.f32 %0, %1;" : "=r"(u) : "f"(x)); return u;
}
__device__ __forceinline__ void mma_tf32(float* d, const unsigned* a, const unsigned* b) {
    asm volatile(
        "mma.sync.aligned.m16n8k8.row.col.f32.tf32.tf32.f32 "
        "{%0,%1,%2,%3},{%4,%5,%6,%7},{%8,%9},{%0,%1,%2,%3};"
        : "+f"(d[0]), "+f"(d[1]), "+f"(d[2]), "+f"(d[3])
        : "r"(a[0]), "r"(a[1]), "r"(a[2]), "r"(a[3]), "r"(b[0]), "r"(b[1]));
}

// ---------------------------------------------------------------------------
// tf32 tensor-core GEMM: XP[r][n] = A[r][:] . W[n][:] + (b_ih[n]+b_hh[n])
//   r = t*64+b;  amode 0: A=embeds (B,T,E), row r -> ((r&63)*512 + (r>>6))*768
//                amode 1: A=g_H0 (row-major 256)
//   n<512 -> W0/bias0 (fwd), else W1/bias1 (rev)
// Tile: BM=128, BN=128, BK=16. 8 warps (2m x 4n), warp tile 64x32.
// SMEM k-major with stride 136 (conflict-free fragment loads).
// ---------------------------------------------------------------------------
#define GBK 16
#define ASTR 136

__global__ __launch_bounds__(256) void gemm_tc(
    const float* __restrict__ Aext, int amode, int Kdim,
    const float* __restrict__ W0, const float* __restrict__ W1,
    const float* __restrict__ bi0, const float* __restrict__ bh0,
    const float* __restrict__ bi1, const float* __restrict__ bh1)
{
    __shared__ float As[GBK * ASTR];
    __shared__ float Bs[GBK * ASTR];
    __shared__ float bias[128];

    const float* A = (amode == 0) ? Aext : g_H0;
    const int tid  = threadIdx.x;
    const int lane = tid & 31, wid = tid >> 5;
    const int wm = wid >> 2, wn = wid & 3;        // 2 x 4 warp grid
    const int g = lane >> 2, tig = lane & 3;
    const int row0 = blockIdx.y * 128;
    const int col0 = blockIdx.x * 128;

    if (tid < 128) {
        int n = col0 + tid;
        bias[tid] = (n < 512) ? (bi0[n] + bh0[n]) : (bi1[n - 512] + bh1[n - 512]);
    }

    // global load mapping: 2048 floats per tile each for A and B
    const int arow = tid >> 1;
    const int ak   = (tid & 1) * 8;
    size_t aoff;
    {
        int r = row0 + arow;
        aoff = (amode == 0) ? ((size_t)(r & 63) * 512 + (size_t)(r >> 6)) * 768
                            : (size_t)r * (size_t)Kdim;
    }
    const int nG = col0 + (tid >> 1);
    const float* wrow = (nG < 512) ? (W0 + (size_t)nG * Kdim)
                                   : (W1 + (size_t)(nG - 512) * Kdim);

    float c[4][4][4];
#pragma unroll
    for (int i = 0; i < 4; i++)
#pragma unroll
        for (int j = 0; j < 4; j++)
#pragma unroll
            for (int q = 0; q < 4; q++) c[i][j][q] = 0.f;

#pragma unroll 1
    for (int k0 = 0; k0 < Kdim; k0 += GBK) {
        float4 av0 = *reinterpret_cast<const float4*>(A + aoff + k0 + ak);
        float4 av1 = *reinterpret_cast<const float4*>(A + aoff + k0 + ak + 4);
        float4 bv0 = *reinterpret_cast<const float4*>(wrow + k0 + ak);
        float4 bv1 = *reinterpret_cast<const float4*>(wrow + k0 + ak + 4);
        __syncthreads();   // previous iteration's frag reads done
        As[(ak + 0) * ASTR + arow] = __uint_as_float(f2tf32(av0.x));
        As[(ak + 1) * ASTR + arow] = __uint_as_float(f2tf32(av0.y));
        As[(ak + 2) * ASTR + arow] = __uint_as_float(f2tf32(av0.z));
        As[(ak + 3) * ASTR + arow] = __uint_as_float(f2tf32(av0.w));
        As[(ak + 4) * ASTR + arow] = __uint_as_float(f2tf32(av1.x));
        As[(ak + 5) * ASTR + arow] = __uint_as_float(f2tf32(av1.y));
        As[(ak + 6) * ASTR + arow] = __uint_as_float(f2tf32(av1.z));
        As[(ak + 7) * ASTR + arow] = __uint_as_float(f2tf32(av1.w));
        Bs[(ak + 0) * ASTR + arow] = __uint_as_float(f2tf32(bv0.x));
        Bs[(ak + 1) * ASTR + arow] = __uint_as_float(f2tf32(bv0.y));
        Bs[(ak + 2) * ASTR + arow] = __uint_as_float(f2tf32(bv0.z));
        Bs[(ak + 3) * ASTR + arow] = __uint_as_float(f2tf32(bv0.w));
        Bs[(ak + 4) * ASTR + arow] = __uint_as_float(f2tf32(bv1.x));
        Bs[(ak + 5) * ASTR + arow] = __uint_as_float(f2tf32(bv1.y));
        Bs[(ak + 6) * ASTR + arow] = __uint_as_float(f2tf32(bv1.z));
        Bs[(ak + 7) * ASTR + arow] = __uint_as_float(f2tf32(bv1.w));
        __syncthreads();

#pragma unroll
        for (int kk = 0; kk < GBK; kk += 8) {
            unsigned af[4][4], bf[4][2];
#pragma unroll
            for (int mt = 0; mt < 4; ++mt) {
                int m0 = wm * 64 + mt * 16;
                af[mt][0] = __float_as_uint(As[(kk + tig) * ASTR + m0 + g]);
                af[mt][1] = __float_as_uint(As[(kk + tig) * ASTR + m0 + g + 8]);
                af[mt][2] = __float_as_uint(As[(kk + tig + 4) * ASTR + m0 + g]);
                af[mt][3] = __float_as_uint(As[(kk + tig + 4) * ASTR + m0 + g + 8]);
            }
#pragma unroll
            for (int nt = 0; nt < 4; ++nt) {
                int n0 = wn * 32 + nt * 8;
                bf[nt][0] = __float_as_uint(Bs[(kk + tig) * ASTR + n0 + g]);
                bf[nt][1] = __float_as_uint(Bs[(kk + tig + 4) * ASTR + n0 + g]);
            }
#pragma unroll
            for (int mt = 0; mt < 4; ++mt)
#pragma unroll
                for (int nt = 0; nt < 4; ++nt)
                    mma_tf32(c[mt][nt], af[mt], bf[nt]);
        }
    }

    // epilogue: D(row,col) with bias
#pragma unroll
    for (int mt = 0; mt < 4; ++mt) {
#pragma unroll
        for (int nt = 0; nt < 4; ++nt) {
            int r  = row0 + wm * 64 + mt * 16 + g;
            int cb = wn * 32 + nt * 8 + 2 * tig;
            int col = col0 + cb;
            float2 v0, v1;
            v0.x = c[mt][nt][0] + bias[cb];
            v0.y = c[mt][nt][1] + bias[cb + 1];
            v1.x = c[mt][nt][2] + bias[cb];
            v1.y = c[mt][nt][3] + bias[cb + 1];
            *reinterpret_cast<float2*>(&g_XP[(size_t)r * 1024 + col]) = v0;
            *reinterpret_cast<float2*>(&g_XP[(size_t)(r + 8) * 1024 + col]) = v1;
        }
    }
}

// ---------------------------------------------------------------------------
// LSTM recurrence: one block per (batch, dir). 512 threads = 16 warps.
// Warp w, lane l: hidden unit u = w*8 + (l&7), gate = l>>3.
// Thread holds its 128 fp16 weights in registers (64 half2).
// h double-buffered in SMEM (broadcast uint4 reads); gates exchanged via shfl.
// One __syncthreads per step.
// ---------------------------------------------------------------------------
__global__ __launch_bounds__(512) void lstm_kernel(
    const float* __restrict__ whh_fwd, const float* __restrict__ whh_rev, int layer)
{
    __shared__ uint4 hbuf4[2][16];   // 2 x 128 halves

    float* Hout = layer ? g_H1 : g_H0;
    const int b   = blockIdx.x >> 1;
    const int dir = blockIdx.x & 1;
    const float* whh = dir ? whh_rev : whh_fwd;

    const int lane = threadIdx.x & 31;
    const int wid  = threadIdx.x >> 5;
    const int u    = wid * 8 + (lane & 7);
    const int gate = lane >> 3;
    const int wrow_idx = gate * 128 + u;

    // weights -> registers (fp16)
    __half2 W[64];
    {
        const float4* wr4 = reinterpret_cast<const float4*>(whh + (size_t)wrow_idx * 128);
#pragma unroll
        for (int i = 0; i < 32; ++i) {
            float4 f = wr4[i];
            W[2 * i]     = __floats2half2_rn(f.x, f.y);
            W[2 * i + 1] = __floats2half2_rn(f.z, f.w);
        }
    }
    if (threadIdx.x < 16) {
        hbuf4[0][threadIdx.x] = make_uint4(0u, 0u, 0u, 0u);
    }
    float cst = 0.f;
    __syncthreads();

    const float* xp_t = g_XP + (size_t)b * 1024 + dir * 512 + wrow_idx;
    float xp = xp_t[(size_t)(dir ? (TT - 1) : 0) * (BB * 1024)];

    for (int t = 0; t < TT; ++t) {
        const int tt = dir ? (TT - 1 - t) : t;
        // prefetch next step's xp
        float xpn = 0.f;
        if (t < TT - 1) {
            int ttn = dir ? (TT - 2 - t) : (t + 1);
            xpn = xp_t[(size_t)ttn * (BB * 1024)];
        }

        const int p = t & 1;
        const uint4* hb = hbuf4[p];
        float acc = 0.f;
#pragma unroll
        for (int k = 0; k < 8; ++k) {
            uint4 ha = hb[2 * k];
            uint4 hc = hb[2 * k + 1];
            __half2 s = __floats2half2_rn(0.f, 0.f);
            s = __hfma2(W[8 * k + 0], u2h2(ha.x), s);
            s = __hfma2(W[8 * k + 1], u2h2(ha.y), s);
            s = __hfma2(W[8 * k + 2], u2h2(ha.z), s);
            s = __hfma2(W[8 * k + 3], u2h2(ha.w), s);
            s = __hfma2(W[8 * k + 4], u2h2(hc.x), s);
            s = __hfma2(W[8 * k + 5], u2h2(hc.y), s);
            s = __hfma2(W[8 * k + 6], u2h2(hc.z), s);
            s = __hfma2(W[8 * k + 7], u2h2(hc.w), s);
            float2 f = __half22float2(s);
            acc += f.x + f.y;
        }
        const float gval = acc + xp;

        // gather the 4 gates of unit u to lanes 0..7
        const int src = lane & 7;
        float iv = __shfl_sync(0xffffffffu, gval, src);
        float fv = __shfl_sync(0xffffffffu, gval, src + 8);
        float gv = __shfl_sync(0xffffffffu, gval, src + 16);
        float ov = __shfl_sync(0xffffffffu, gval, src + 24);

        if (lane < 8) {
            float cn = sigf(fv) * cst + sigf(iv) * tanhfast(gv);
            cst = cn;
            float hn = sigf(ov) * tanhfast(cn);
            reinterpret_cast<__half*>(&hbuf4[1 - p][0])[u] = __float2half_rn(hn);
            Hout[((size_t)tt * BB + b) * 256 + dir * 128 + u] = hn;
        }
        xp = xpn;
        __syncthreads();
    }
}

// ---------------------------------------------------------------------------
// Emissions: EM[r][n] = H1[r][:] . linear_w[n][:] + linear_b[n], n padded to 16
// ---------------------------------------------------------------------------
__global__ __launch_bounds__(256) void emis_kernel(
    const float* __restrict__ lw, const float* __restrict__ lb)
{
    const int r = blockIdx.x * 16 + (threadIdx.x >> 4);
    const int n = threadIdx.x & 15;
    float acc = 0.f;
    if (n < KK) {
        const float4* h4 = reinterpret_cast<const float4*>(&g_H1[(size_t)r * 256]);
        const float4* w4 = reinterpret_cast<const float4*>(lw + (size_t)n * 256);
#pragma unroll 8
        for (int k = 0; k < 64; ++k) {
            float4 a = h4[k], w = w4[k];
            acc += a.x * w.x + a.y * w.y + a.z * w.z + a.w * w.w;
        }
        acc += lb[n];
    }
    g_EM[(size_t)r * 16 + n] = acc;
}

// ---------------------------------------------------------------------------
// CRF: one block per batch.
// ---------------------------------------------------------------------------
__global__ __launch_bounds__(256) void crf_kernel(
    const int* __restrict__ tags, const void* __restrict__ maskraw,
    const float* __restrict__ start_t, const float* __restrict__ end_t,
    const float* __restrict__ trans)
{
    __shared__ float ems[TT * 12];
    __shared__ float redf[256];
    __shared__ int   redi[256];
    __shared__ unsigned char maskb[TT];
    __shared__ float s_num;

    const int b = blockIdx.x;
    const int tid = threadIdx.x;

    {
        const unsigned char* mc = reinterpret_cast<const unsigned char*>(maskraw);
        const bool bytewise = (mc[1] != 0);
        const int* mi = reinterpret_cast<const int*>(maskraw);
        for (int t = tid; t < TT; t += 256) {
            maskb[t] = bytewise ? (mc[(size_t)b * TT + t] != 0)
                                : (mi[(size_t)b * TT + t] != 0);
        }
    }
    for (int base = tid; base < TT * 16; base += 256) {
        int t = base >> 4, j = base & 15;
        if (j < KK) ems[t * 12 + j] = g_EM[((size_t)t * BB + b) * 16 + j];
    }
    __syncthreads();

    float part = 0.f;
    int   cnt  = 0;
    for (int t = tid; t < TT; t += 256) cnt += maskb[t] ? 1 : 0;
    for (int t = 1 + tid; t < TT; t += 256) {
        if (maskb[t]) {
            int tp = tags[(size_t)b * TT + t - 1];
            int tc = tags[(size_t)b * TT + t];
            part += trans[tp * KK + tc] + ems[t * 12 + tc];
        }
    }
    redf[tid] = part; redi[tid] = cnt;
    __syncthreads();
    for (int s = 128; s > 0; s >>= 1) {
        if (tid < s) { redf[tid] += redf[tid + s]; redi[tid] += redi[tid + s]; }
        __syncthreads();
    }
    if (tid == 0) {
        int t0 = tags[(size_t)b * TT];
        int seqEnd = redi[0] - 1;
        s_num = start_t[t0] + ems[t0] + redf[0]
              + end_t[tags[(size_t)b * TT + seqEnd]];
    }
    __syncthreads();

    if (tid < 32) {
        const int lane = tid;
        float tcol[KK];
        if (lane < KK) {
#pragma unroll
            for (int i = 0; i < KK; i++) tcol[i] = trans[i * KK + lane];
        } else {
#pragma unroll
            for (int i = 0; i < KK; i++) tcol[i] = 0.f;
        }
        float score = (lane < KK) ? (start_t[lane] + ems[lane]) : -1e30f;

        for (int t = 1; t < TT; ++t) {
            if (maskb[t]) {
                float vi[KK];
                float m = -1e30f;
#pragma unroll
                for (int i = 0; i < KK; i++) {
                    float si = __shfl_sync(0xffffffffu, score, i);
                    vi[i] = si + tcol[i];
                    m = fmaxf(m, vi[i]);
                }
                float ssum = 0.f;
#pragma unroll
                for (int i = 0; i < KK; i++) ssum += __expf(vi[i] - m);
                float nxt = m + __logf(ssum) + ems[t * 12 + lane];
                if (lane < KK) score = nxt;
            }
        }
        float v = (lane < KK) ? (score + end_t[lane]) : -1e30f;
        float m = v;
#pragma unroll
        for (int off = 16; off > 0; off >>= 1)
            m = fmaxf(m, __shfl_xor_sync(0xffffffffu, m, off));
        float e = __expf(v - m);
#pragma unroll
        for (int off = 16; off > 0; off >>= 1)
            e += __shfl_xor_sync(0xffffffffu, e, off);
        float den = m + __logf(e);
        if (lane == 0) g_ND[b] = s_num - den;
    }
}

__global__ void finish_kernel(float* __restrict__ out, int out_n)
{
    __shared__ float s[64];
    int tid = threadIdx.x;
    s[tid] = g_ND[tid];
    __syncthreads();
    for (int st = 32; st > 0; st >>= 1) {
        if (tid < st) s[tid] += s[tid + st];
        __syncthreads();
    }
    if (tid == 0) out[0] = -s[0] / 64.f;
    if (tid > 0 && tid < out_n) out[tid] = 0.f;
}

// ---------------------------------------------------------------------------
extern "C" void kernel_launch(void* const* d_in, const int* in_sizes, int n_in,
                              void* d_out, int out_size)
{
    const float* embeds    = (const float*)d_in[0];
    const int*   tags      = (const int*)d_in[1];
    const void*  mask      = d_in[2];
    const float* w_ih_l0   = (const float*)d_in[3];
    const float* w_hh_l0   = (const float*)d_in[4];
    const float* b_ih_l0   = (const float*)d_in[5];
    const float* b_hh_l0   = (const float*)d_in[6];
    const float* w_ih_l0r  = (const float*)d_in[7];
    const float* w_hh_l0r  = (const float*)d_in[8];
    const float* b_ih_l0r  = (const float*)d_in[9];
    const float* b_hh_l0r  = (const float*)d_in[10];
    const float* w_ih_l1   = (const float*)d_in[11];
    const float* w_hh_l1   = (const float*)d_in[12];
    const float* b_ih_l1   = (const float*)d_in[13];
    const float* b_hh_l1   = (const float*)d_in[14];
    const float* w_ih_l1r  = (const float*)d_in[15];
    const float* w_hh_l1r  = (const float*)d_in[16];
    const float* b_ih_l1r  = (const float*)d_in[17];
    const float* b_hh_l1r  = (const float*)d_in[18];
    const float* linear_w  = (const float*)d_in[19];
    const float* linear_b  = (const float*)d_in[20];
    const float* start_tr  = (const float*)d_in[21];
    const float* end_tr    = (const float*)d_in[22];
    const float* trans     = (const float*)d_in[23];
    (void)in_sizes; (void)n_in;

    dim3 ggrid(8, 256);   // N/128 x M/128

    // layer 0
    gemm_tc<<<ggrid, 256>>>(embeds, 0, 768,
                            w_ih_l0, w_ih_l0r, b_ih_l0, b_hh_l0, b_ih_l0r, b_hh_l0r);
    lstm_kernel<<<128, 512>>>(w_hh_l0, w_hh_l0r, 0);

    // layer 1
    gemm_tc<<<ggrid, 256>>>(embeds, 1, 256,
                            w_ih_l1, w_ih_l1r, b_ih_l1, b_hh_l1, b_ih_l1r, b_hh_l1r);
    lstm_kernel<<<128, 512>>>(w_hh_l1, w_hh_l1r, 1);

    // emissions + CRF
    emis_kernel<<<2048, 256>>>(linear_w, linear_b);
    crf_kernel<<<64, 256>>>(tags, mask, start_tr, end_tr, trans);
    finish_kernel<<<1, 64>>>((float*)d_out, out_size);
}

// round 3
// speedup vs baseline: 2.4145x; 1.2283x over previous
#include <cuda_runtime.h>
#include <cuda_fp16.h>
#include <cuda_bf16.h>

// Problem constants
#define BB 64
#define TT 512
#define EE 768
#define HH 128      // hidden per direction
#define KK 11

// ---------------------------------------------------------------------------
// Scratch (device globals; no dynamic allocation allowed)
// ---------------------------------------------------------------------------
__device__ float g_XP[(size_t)TT * BB * 1024];   // gate x-contributions, [t][b][dir*512+g]
__device__ float g_H0[(size_t)TT * BB * 256];    // layer0 output  [t][b][dir*128+h]
__device__ float g_H1[(size_t)TT * BB * 256];    // layer1 output
__device__ float g_EM[(size_t)TT * BB * 16];     // emissions padded to 16
__device__ float g_ND[BB];                       // num - den per batch

__device__ __forceinline__ float sigf(float x) { return 1.f / (1.f + __expf(-x)); }
__device__ __forceinline__ float tanhfast(float x) { return 2.f * sigf(2.f * x) - 1.f; }

__device__ __forceinline__ __half2 u2h2(unsigned int u) {
    __half2 r; *reinterpret_cast<unsigned int*>(&r) = u; return r;
}
__device__ __forceinline__ unsigned h2u(__half2 h) {
    return *reinterpret_cast<unsigned*>(&h);
}
__device__ __forceinline__ void mma_f16(float* d, const unsigned* a, const unsigned* b) {
    asm volatile(
        "mma.sync.aligned.m16n8k16.row.col.f32.f16.f16.f32 "
        "{%0,%1,%2,%3},{%4,%5,%6,%7},{%8,%9},{%0,%1,%2,%3};"
        : "+f"(d[0]), "+f"(d[1]), "+f"(d[2]), "+f"(d[3])
        : "r"(a[0]), "r"(a[1]), "r"(a[2]), "r"(a[3]), "r"(b[0]), "r"(b[1]));
}

// ---------------------------------------------------------------------------
// fp16 tensor-core GEMM (fp32 accum): XP[r][n] = A[r][:].W[n][:] + bias[n]
//   r = t*64+b;  amode 0: A=embeds (B,T,E), row r -> ((r&63)*512 + (r>>6))*768
//                amode 1: A=g_H0 (row-major 256)
//   n<512 -> W0/bias0 (fwd), else W1/bias1 (rev)
// Tile BM=128, BN=128, BK=16; 8 warps (2m x 4n), warp tile 64x32.
// SMEM: half2, k2-major [k2][m], stride 136 (conflict-free frags), double buffer.
// ---------------------------------------------------------------------------
#define GBK 16
#define HSTR 136

__global__ __launch_bounds__(256) void gemm_tc(
    const float* __restrict__ Aext, int amode, int Kdim,
    const float* __restrict__ W0, const float* __restrict__ W1,
    const float* __restrict__ bi0, const float* __restrict__ bh0,
    const float* __restrict__ bi1, const float* __restrict__ bh1)
{
    __shared__ unsigned As2[2][8 * HSTR];
    __shared__ unsigned Bs2[2][8 * HSTR];
    __shared__ float bias[128];

    const float* A = (amode == 0) ? Aext : g_H0;
    const int tid  = threadIdx.x;
    const int lane = tid & 31, wid = tid >> 5;
    const int wm = wid >> 2, wn = wid & 3;        // 2 x 4 warp grid
    const int g = lane >> 2, tig = lane & 3;
    const int row0 = blockIdx.y * 128;
    const int col0 = blockIdx.x * 128;

    if (tid < 128) {
        int n = col0 + tid;
        bias[tid] = (n < 512) ? (bi0[n] + bh0[n]) : (bi1[n - 512] + bh1[n - 512]);
    }

    // global load mapping: per thread 8 floats of A, 8 of B per k-tile
    const int arow = tid >> 1;             // 0..127
    const int ak   = (tid & 1) * 8;        // 0 or 8
    const int ak2  = ak >> 1;              // 0 or 4
    size_t aoff;
    {
        int r = row0 + arow;
        aoff = (amode == 0) ? ((size_t)(r & 63) * 512 + (size_t)(r >> 6)) * 768
                            : (size_t)r * (size_t)Kdim;
    }
    const int nG = col0 + arow;
    const float* wrow = (nG < 512) ? (W0 + (size_t)nG * Kdim)
                                   : (W1 + (size_t)(nG - 512) * Kdim);

    float c[4][4][4];
#pragma unroll
    for (int i = 0; i < 4; i++)
#pragma unroll
        for (int j = 0; j < 4; j++)
#pragma unroll
            for (int q = 0; q < 4; q++) c[i][j][q] = 0.f;

    const int niter = Kdim / GBK;
    float4 av0, av1, bv0, bv1;

    // prologue: tile 0 -> buf 0
    av0 = *reinterpret_cast<const float4*>(A + aoff + ak);
    av1 = *reinterpret_cast<const float4*>(A + aoff + ak + 4);
    bv0 = *reinterpret_cast<const float4*>(wrow + ak);
    bv1 = *reinterpret_cast<const float4*>(wrow + ak + 4);
    As2[0][(ak2 + 0) * HSTR + arow] = h2u(__floats2half2_rn(av0.x, av0.y));
    As2[0][(ak2 + 1) * HSTR + arow] = h2u(__floats2half2_rn(av0.z, av0.w));
    As2[0][(ak2 + 2) * HSTR + arow] = h2u(__floats2half2_rn(av1.x, av1.y));
    As2[0][(ak2 + 3) * HSTR + arow] = h2u(__floats2half2_rn(av1.z, av1.w));
    Bs2[0][(ak2 + 0) * HSTR + arow] = h2u(__floats2half2_rn(bv0.x, bv0.y));
    Bs2[0][(ak2 + 1) * HSTR + arow] = h2u(__floats2half2_rn(bv0.z, bv0.w));
    Bs2[0][(ak2 + 2) * HSTR + arow] = h2u(__floats2half2_rn(bv1.x, bv1.y));
    Bs2[0][(ak2 + 3) * HSTR + arow] = h2u(__floats2half2_rn(bv1.z, bv1.w));
    __syncthreads();

#pragma unroll 1
    for (int i = 0; i < niter; ++i) {
        const int pb = i & 1;
        if (i + 1 < niter) {
            const int k0 = (i + 1) * GBK;
            av0 = *reinterpret_cast<const float4*>(A + aoff + k0 + ak);
            av1 = *reinterpret_cast<const float4*>(A + aoff + k0 + ak + 4);
            bv0 = *reinterpret_cast<const float4*>(wrow + k0 + ak);
            bv1 = *reinterpret_cast<const float4*>(wrow + k0 + ak + 4);
        }

        // compute tile i from buf pb
        {
            unsigned af[4][4], bf[4][2];
#pragma unroll
            for (int mt = 0; mt < 4; ++mt) {
                int m0 = wm * 64 + mt * 16;
                af[mt][0] = As2[pb][tig * HSTR + m0 + g];
                af[mt][1] = As2[pb][tig * HSTR + m0 + g + 8];
                af[mt][2] = As2[pb][(tig + 4) * HSTR + m0 + g];
                af[mt][3] = As2[pb][(tig + 4) * HSTR + m0 + g + 8];
            }
#pragma unroll
            for (int nt = 0; nt < 4; ++nt) {
                int n0 = wn * 32 + nt * 8;
                bf[nt][0] = Bs2[pb][tig * HSTR + n0 + g];
                bf[nt][1] = Bs2[pb][(tig + 4) * HSTR + n0 + g];
            }
#pragma unroll
            for (int mt = 0; mt < 4; ++mt)
#pragma unroll
                for (int nt = 0; nt < 4; ++nt)
                    mma_f16(c[mt][nt], af[mt], bf[nt]);
        }

        if (i + 1 < niter) {
            const int nb = pb ^ 1;
            As2[nb][(ak2 + 0) * HSTR + arow] = h2u(__floats2half2_rn(av0.x, av0.y));
            As2[nb][(ak2 + 1) * HSTR + arow] = h2u(__floats2half2_rn(av0.z, av0.w));
            As2[nb][(ak2 + 2) * HSTR + arow] = h2u(__floats2half2_rn(av1.x, av1.y));
            As2[nb][(ak2 + 3) * HSTR + arow] = h2u(__floats2half2_rn(av1.z, av1.w));
            Bs2[nb][(ak2 + 0) * HSTR + arow] = h2u(__floats2half2_rn(bv0.x, bv0.y));
            Bs2[nb][(ak2 + 1) * HSTR + arow] = h2u(__floats2half2_rn(bv0.z, bv0.w));
            Bs2[nb][(ak2 + 2) * HSTR + arow] = h2u(__floats2half2_rn(bv1.x, bv1.y));
            Bs2[nb][(ak2 + 3) * HSTR + arow] = h2u(__floats2half2_rn(bv1.z, bv1.w));
        }
        __syncthreads();
    }

    // epilogue: D(row,col) with bias
#pragma unroll
    for (int mt = 0; mt < 4; ++mt) {
#pragma unroll
        for (int nt = 0; nt < 4; ++nt) {
            int r  = row0 + wm * 64 + mt * 16 + g;
            int cb = wn * 32 + nt * 8 + 2 * tig;
            int col = col0 + cb;
            float2 v0, v1;
            v0.x = c[mt][nt][0] + bias[cb];
            v0.y = c[mt][nt][1] + bias[cb + 1];
            v1.x = c[mt][nt][2] + bias[cb];
            v1.y = c[mt][nt][3] + bias[cb + 1];
            *reinterpret_cast<float2*>(&g_XP[(size_t)r * 1024 + col]) = v0;
            *reinterpret_cast<float2*>(&g_XP[(size_t)(r + 8) * 1024 + col]) = v1;
        }
    }
}

// ---------------------------------------------------------------------------
// LSTM recurrence: one block per (batch, dir). 512 threads = 16 warps.
// Warp w, lane l: hidden unit u = w*8 + (l&7), gate = l>>3.
// Weights in registers (fp16); h double-buffered in SMEM; activations applied
// pre-shfl; half2 accumulation with 4 independent chains; pointer marching.
// ---------------------------------------------------------------------------
__global__ __launch_bounds__(512) void lstm_kernel(
    const float* __restrict__ whh_fwd, const float* __restrict__ whh_rev, int layer)
{
    __shared__ uint4 hbuf4[2][16];   // 2 x 128 halves

    float* Hout = layer ? g_H1 : g_H0;
    const int b   = blockIdx.x >> 1;
    const int dir = blockIdx.x & 1;
    const float* whh = dir ? whh_rev : whh_fwd;

    const int lane = threadIdx.x & 31;
    const int wid  = threadIdx.x >> 5;
    const int u    = wid * 8 + (lane & 7);
    const int gate = lane >> 3;
    const int wrow_idx = gate * 128 + u;

    // weights -> registers (fp16)
    __half2 W[64];
    {
        const float4* wr4 = reinterpret_cast<const float4*>(whh + (size_t)wrow_idx * 128);
#pragma unroll
        for (int i = 0; i < 32; ++i) {
            float4 f = wr4[i];
            W[2 * i]     = __floats2half2_rn(f.x, f.y);
            W[2 * i + 1] = __floats2half2_rn(f.z, f.w);
        }
    }
    if (threadIdx.x < 16) hbuf4[0][threadIdx.x] = make_uint4(0u, 0u, 0u, 0u);
    float cst = 0.f;
    __syncthreads();

    const long xstride = dir ? -(long)(BB * 1024) : (long)(BB * 1024);
    const long hstride = dir ? -(long)(BB * 256)  : (long)(BB * 256);
    const float* xp_p = g_XP + (size_t)(dir ? (TT - 1) : 0) * (BB * 1024)
                             + (size_t)b * 1024 + dir * 512 + wrow_idx;
    float* hout_p = Hout + (size_t)(dir ? (TT - 1) : 0) * (BB * 256)
                         + (size_t)b * 256 + dir * 128 + u;

    float xp = *xp_p;

    for (int t = 0; t < TT; ++t) {
        // prefetch next step's xp (clamped pointer on last step)
        const float* pf = xp_p + ((t < TT - 1) ? xstride : 0);
        float xpn = *pf;

        const uint4* hb = hbuf4[t & 1];
        __half2 s0 = __floats2half2_rn(0.f, 0.f);
        __half2 s1 = s0, s2 = s0, s3 = s0;
#pragma unroll
        for (int k = 0; k < 4; ++k) {
            uint4 ha = hb[4 * k];
            uint4 hc = hb[4 * k + 1];
            uint4 hd = hb[4 * k + 2];
            uint4 he = hb[4 * k + 3];
            s0 = __hfma2(W[16 * k + 0],  u2h2(ha.x), s0);
            s1 = __hfma2(W[16 * k + 1],  u2h2(ha.y), s1);
            s2 = __hfma2(W[16 * k + 2],  u2h2(ha.z), s2);
            s3 = __hfma2(W[16 * k + 3],  u2h2(ha.w), s3);
            s0 = __hfma2(W[16 * k + 4],  u2h2(hc.x), s0);
            s1 = __hfma2(W[16 * k + 5],  u2h2(hc.y), s1);
            s2 = __hfma2(W[16 * k + 6],  u2h2(hc.z), s2);
            s3 = __hfma2(W[16 * k + 7],  u2h2(hc.w), s3);
            s0 = __hfma2(W[16 * k + 8],  u2h2(hd.x), s0);
            s1 = __hfma2(W[16 * k + 9],  u2h2(hd.y), s1);
            s2 = __hfma2(W[16 * k + 10], u2h2(hd.z), s2);
            s3 = __hfma2(W[16 * k + 11], u2h2(hd.w), s3);
            s0 = __hfma2(W[16 * k + 12], u2h2(he.x), s0);
            s1 = __hfma2(W[16 * k + 13], u2h2(he.y), s1);
            s2 = __hfma2(W[16 * k + 14], u2h2(he.z), s2);
            s3 = __hfma2(W[16 * k + 15], u2h2(he.w), s3);
        }
        __half2 sh = __hadd2(__hadd2(s0, s1), __hadd2(s2, s3));
        float2 f2 = __half22float2(sh);
        const float gval = f2.x + f2.y + xp;

        // activation applied by the owning lane (sigmoid for i,f,o; tanh for g)
        const float act = (gate == 2) ? tanhfast(gval) : sigf(gval);

        const int src = lane & 7;
        float iv = __shfl_sync(0xffffffffu, act, src);
        float fv = __shfl_sync(0xffffffffu, act, src + 8);
        float gv = __shfl_sync(0xffffffffu, act, src + 16);
        float ov = __shfl_sync(0xffffffffu, act, src + 24);

        if (lane < 8) {
            float cn = fv * cst + iv * gv;
            cst = cn;
            float hn = ov * tanhfast(cn);
            reinterpret_cast<__half*>(&hbuf4[(t & 1) ^ 1][0])[u] = __float2half_rn(hn);
            *hout_p = hn;
        }
        xp = xpn;
        xp_p += xstride;
        hout_p += hstride;
        __syncthreads();
    }
}

// ---------------------------------------------------------------------------
// Emissions: EM[r][n] = H1[r][:] . linear_w[n][:] + linear_b[n], n padded to 16
// ---------------------------------------------------------------------------
__global__ __launch_bounds__(256) void emis_kernel(
    const float* __restrict__ lw, const float* __restrict__ lb)
{
    const int r = blockIdx.x * 16 + (threadIdx.x >> 4);
    const int n = threadIdx.x & 15;
    float acc = 0.f;
    if (n < KK) {
        const float4* h4 = reinterpret_cast<const float4*>(&g_H1[(size_t)r * 256]);
        const float4* w4 = reinterpret_cast<const float4*>(lw + (size_t)n * 256);
#pragma unroll 8
        for (int k = 0; k < 64; ++k) {
            float4 a = h4[k], w = w4[k];
            acc += a.x * w.x + a.y * w.y + a.z * w.z + a.w * w.w;
        }
        acc += lb[n];
    }
    g_EM[(size_t)r * 16 + n] = acc;
}

// ---------------------------------------------------------------------------
// CRF: one block per batch.
// ---------------------------------------------------------------------------
__global__ __launch_bounds__(256) void crf_kernel(
    const int* __restrict__ tags, const void* __restrict__ maskraw,
    const float* __restrict__ start_t, const float* __restrict__ end_t,
    const float* __restrict__ trans)
{
    __shared__ float ems[TT * 12];
    __shared__ float redf[256];
    __shared__ int   redi[256];
    __shared__ unsigned char maskb[TT];
    __shared__ float s_num;

    const int b = blockIdx.x;
    const int tid = threadIdx.x;

    {
        const unsigned char* mc = reinterpret_cast<const unsigned char*>(maskraw);
        const bool bytewise = (mc[1] != 0);
        const int* mi = reinterpret_cast<const int*>(maskraw);
        for (int t = tid; t < TT; t += 256) {
            maskb[t] = bytewise ? (mc[(size_t)b * TT + t] != 0)
                                : (mi[(size_t)b * TT + t] != 0);
        }
    }
    for (int base = tid; base < TT * 16; base += 256) {
        int t = base >> 4, j = base & 15;
        if (j < KK) ems[t * 12 + j] = g_EM[((size_t)t * BB + b) * 16 + j];
    }
    __syncthreads();

    float part = 0.f;
    int   cnt  = 0;
    for (int t = tid; t < TT; t += 256) cnt += maskb[t] ? 1 : 0;
    for (int t = 1 + tid; t < TT; t += 256) {
        if (maskb[t]) {
            int tp = tags[(size_t)b * TT + t - 1];
            int tc = tags[(size_t)b * TT + t];
            part += trans[tp * KK + tc] + ems[t * 12 + tc];
        }
    }
    redf[tid] = part; redi[tid] = cnt;
    __syncthreads();
    for (int s = 128; s > 0; s >>= 1) {
        if (tid < s) { redf[tid] += redf[tid + s]; redi[tid] += redi[tid + s]; }
        __syncthreads();
    }
    if (tid == 0) {
        int t0 = tags[(size_t)b * TT];
        int seqEnd = redi[0] - 1;
        s_num = start_t[t0] + ems[t0] + redf[0]
              + end_t[tags[(size_t)b * TT + seqEnd]];
    }
    __syncthreads();

    if (tid < 32) {
        const int lane = tid;
        float tcol[KK];
        if (lane < KK) {
#pragma unroll
            for (int i = 0; i < KK; i++) tcol[i] = trans[i * KK + lane];
        } else {
#pragma unroll
            for (int i = 0; i < KK; i++) tcol[i] = 0.f;
        }
        float score = (lane < KK) ? (start_t[lane] + ems[lane]) : -1e30f;

        for (int t = 1; t < TT; ++t) {
            if (maskb[t]) {
                float vi[KK];
                float m = -1e30f;
#pragma unroll
                for (int i = 0; i < KK; i++) {
                    float si = __shfl_sync(0xffffffffu, score, i);
                    vi[i] = si + tcol[i];
                    m = fmaxf(m, vi[i]);
                }
                float ssum = 0.f;
#pragma unroll
                for (int i = 0; i < KK; i++) ssum += __expf(vi[i] - m);
                float nxt = m + __logf(ssum) + ems[t * 12 + lane];
                if (lane < KK) score = nxt;
            }
        }
        float v = (lane < KK) ? (score + end_t[lane]) : -1e30f;
        float m = v;
#pragma unroll
        for (int off = 16; off > 0; off >>= 1)
            m = fmaxf(m, __shfl_xor_sync(0xffffffffu, m, off));
        float e = __expf(v - m);
#pragma unroll
        for (int off = 16; off > 0; off >>= 1)
            e += __shfl_xor_sync(0xffffffffu, e, off);
        float den = m + __logf(e);
        if (lane == 0) g_ND[b] = s_num - den;
    }
}

__global__ void finish_kernel(float* __restrict__ out, int out_n)
{
    __shared__ float s[64];
    int tid = threadIdx.x;
    s[tid] = g_ND[tid];
    __syncthreads();
    for (int st = 32; st > 0; st >>= 1) {
        if (tid < st) s[tid] += s[tid + st];
        __syncthreads();
    }
    if (tid == 0) out[0] = -s[0] / 64.f;
    if (tid > 0 && tid < out_n) out[tid] = 0.f;
}

// ---------------------------------------------------------------------------
extern "C" void kernel_launch(void* const* d_in, const int* in_sizes, int n_in,
                              void* d_out, int out_size)
{
    const float* embeds    = (const float*)d_in[0];
    const int*   tags      = (const int*)d_in[1];
    const void*  mask      = d_in[2];
    const float* w_ih_l0   = (const float*)d_in[3];
    const float* w_hh_l0   = (const float*)d_in[4];
    const float* b_ih_l0   = (const float*)d_in[5];
    const float* b_hh_l0   = (const float*)d_in[6];
    const float* w_ih_l0r  = (const float*)d_in[7];
    const float* w_hh_l0r  = (const float*)d_in[8];
    const float* b_ih_l0r  = (const float*)d_in[9];
    const float* b_hh_l0r  = (const float*)d_in[10];
    const float* w_ih_l1   = (const float*)d_in[11];
    const float* w_hh_l1   = (const float*)d_in[12];
    const float* b_ih_l1   = (const float*)d_in[13];
    const float* b_hh_l1   = (const float*)d_in[14];
    const float* w_ih_l1r  = (const float*)d_in[15];
    const float* w_hh_l1r  = (const float*)d_in[16];
    const float* b_ih_l1r  = (const float*)d_in[17];
    const float* b_hh_l1r  = (const float*)d_in[18];
    const float* linear_w  = (const float*)d_in[19];
    const float* linear_b  = (const float*)d_in[20];
    const float* start_tr  = (const float*)d_in[21];
    const float* end_tr    = (const float*)d_in[22];
    const float* trans     = (const float*)d_in[23];
    (void)in_sizes; (void)n_in;

    dim3 ggrid(8, 256);   // N/128 x M/128

    // layer 0
    gemm_tc<<<ggrid, 256>>>(embeds, 0, 768,
                            w_ih_l0, w_ih_l0r, b_ih_l0, b_hh_l0, b_ih_l0r, b_hh_l0r);
    lstm_kernel<<<128, 512>>>(w_hh_l0, w_hh_l0r, 0);

    // layer 1
    gemm_tc<<<ggrid, 256>>>(embeds, 1, 256,
                            w_ih_l1, w_ih_l1r, b_ih_l1, b_hh_l1, b_ih_l1r, b_hh_l1r);
    lstm_kernel<<<128, 512>>>(w_hh_l1, w_hh_l1r, 1);

    // emissions + CRF
    emis_kernel<<<2048, 256>>>(linear_w, linear_b);
    crf_kernel<<<64, 256>>>(tags, mask, start_tr, end_tr, trans);
    finish_kernel<<<1, 64>>>((float*)d_out, out_size);
}

// round 4
// speedup vs baseline: 2.5726x; 1.0655x over previous
#include <cuda_runtime.h>
#include <cuda_fp16.h>
#include <cuda_bf16.h>

// Problem constants
#define BB 64
#define TT 512
#define EE 768
#define HH 128      // hidden per direction
#define KK 11

// ---------------------------------------------------------------------------
// Scratch (device globals; no dynamic allocation allowed)
// ---------------------------------------------------------------------------
__device__ float  g_XP[(size_t)TT * BB * 1024];  // gate x-contributions
__device__ __half g_H0h[(size_t)TT * BB * 256];  // layer0 output (half, GEMM input)
__device__ float  g_H1[(size_t)TT * BB * 256];   // layer1 output (fp32, emis input)
__device__ float  g_EM[(size_t)TT * BB * 16];    // emissions padded to 16
__device__ float  g_ND[BB];                      // num - den per batch

__device__ __forceinline__ float tanha(float x) {
    float r; asm("tanh.approx.f32 %0, %1;" : "=f"(r) : "f"(x)); return r;
}
__device__ __forceinline__ float sigt(float x) {   // sigmoid via tanh
    return fmaf(0.5f, tanha(0.5f * x), 0.5f);
}
__device__ __forceinline__ float sigf(float x) { return 1.f / (1.f + __expf(-x)); }

__device__ __forceinline__ __half2 u2h2(unsigned int u) {
    __half2 r; *reinterpret_cast<unsigned int*>(&r) = u; return r;
}
__device__ __forceinline__ unsigned h2u(__half2 h) {
    return *reinterpret_cast<unsigned*>(&h);
}
__device__ __forceinline__ void mma_f16(float* d, const unsigned* a, const unsigned* b) {
    asm volatile(
        "mma.sync.aligned.m16n8k16.row.col.f32.f16.f16.f32 "
        "{%0,%1,%2,%3},{%4,%5,%6,%7},{%8,%9},{%0,%1,%2,%3};"
        : "+f"(d[0]), "+f"(d[1]), "+f"(d[2]), "+f"(d[3])
        : "r"(a[0]), "r"(a[1]), "r"(a[2]), "r"(a[3]), "r"(b[0]), "r"(b[1]));
}

// ---------------------------------------------------------------------------
// fp16 tensor-core GEMM (fp32 accum): XP[r][n] = A[r][:].W[n][:] + bias[n]
//   r = t*64+b;  AMODE 0: A=embeds (B,T,E) fp32, row r -> ((r&63)*512+(r>>6))*768
//                AMODE 1: A=g_H0h (row-major 256, fp16)
//   n<512 -> W0/bias0 (fwd), else W1/bias1 (rev)
// Tile BM=128, BN=128, BK=32; 8 warps (2m x 4n), warp tile 64x32.
// SMEM: half2 k2-major [k2][m], stride 136, double buffer, 1 sync / 32-k.
// ---------------------------------------------------------------------------
#define GBK 32
#define HSTR 136

template<int AMODE>
__global__ __launch_bounds__(256) void gemm_tc(
    const float* __restrict__ Aext, int Kdim,
    const float* __restrict__ W0, const float* __restrict__ W1,
    const float* __restrict__ bi0, const float* __restrict__ bh0,
    const float* __restrict__ bi1, const float* __restrict__ bh1)
{
    __shared__ unsigned As2[2][16 * HSTR];
    __shared__ unsigned Bs2[2][16 * HSTR];
    __shared__ float bias[128];

    const int tid  = threadIdx.x;
    const int lane = tid & 31, wid = tid >> 5;
    const int wm = wid >> 2, wn = wid & 3;        // 2 x 4 warp grid
    const int g = lane >> 2, tig = lane & 3;
    const int row0 = blockIdx.y * 128;
    const int col0 = blockIdx.x * 128;

    if (tid < 128) {
        int n = col0 + tid;
        bias[tid] = (n < 512) ? (bi0[n] + bh0[n]) : (bi1[n - 512] + bh1[n - 512]);
    }

    // global load mapping: per thread 16 values of A, 16 of B per 32-k tile
    const int arow = tid >> 1;             // 0..127
    const int ak   = (tid & 1) * 16;       // 0 or 16
    const int ak2  = ak >> 1;              // 0 or 8
    size_t aoff;
    {
        int r = row0 + arow;
        aoff = (AMODE == 0) ? ((size_t)(r & 63) * 512 + (size_t)(r >> 6)) * 768
                            : (size_t)r * 256;
    }
    const float* Af = Aext;
    const __half* Ah = g_H0h;
    const int nG = col0 + arow;
    const float* wrow = (nG < 512) ? (W0 + (size_t)nG * Kdim)
                                   : (W1 + (size_t)(nG - 512) * Kdim);

    float c[4][4][4];
#pragma unroll
    for (int i = 0; i < 4; i++)
#pragma unroll
        for (int j = 0; j < 4; j++)
#pragma unroll
            for (int q = 0; q < 4; q++) c[i][j][q] = 0.f;

    const int niter = Kdim / GBK;

    float4 av0, av1, av2, av3;     // AMODE 0
    uint4  au0, au1;               // AMODE 1
    float4 bv0, bv1, bv2, bv3;

    // ---- prologue: tile 0 -> buf 0
    if (AMODE == 0) {
        av0 = *reinterpret_cast<const float4*>(Af + aoff + ak);
        av1 = *reinterpret_cast<const float4*>(Af + aoff + ak + 4);
        av2 = *reinterpret_cast<const float4*>(Af + aoff + ak + 8);
        av3 = *reinterpret_cast<const float4*>(Af + aoff + ak + 12);
    } else {
        au0 = *reinterpret_cast<const uint4*>(Ah + aoff + ak);
        au1 = *reinterpret_cast<const uint4*>(Ah + aoff + ak + 8);
    }
    bv0 = *reinterpret_cast<const float4*>(wrow + ak);
    bv1 = *reinterpret_cast<const float4*>(wrow + ak + 4);
    bv2 = *reinterpret_cast<const float4*>(wrow + ak + 8);
    bv3 = *reinterpret_cast<const float4*>(wrow + ak + 12);

    {
        if (AMODE == 0) {
            As2[0][(ak2 + 0) * HSTR + arow] = h2u(__floats2half2_rn(av0.x, av0.y));
            As2[0][(ak2 + 1) * HSTR + arow] = h2u(__floats2half2_rn(av0.z, av0.w));
            As2[0][(ak2 + 2) * HSTR + arow] = h2u(__floats2half2_rn(av1.x, av1.y));
            As2[0][(ak2 + 3) * HSTR + arow] = h2u(__floats2half2_rn(av1.z, av1.w));
            As2[0][(ak2 + 4) * HSTR + arow] = h2u(__floats2half2_rn(av2.x, av2.y));
            As2[0][(ak2 + 5) * HSTR + arow] = h2u(__floats2half2_rn(av2.z, av2.w));
            As2[0][(ak2 + 6) * HSTR + arow] = h2u(__floats2half2_rn(av3.x, av3.y));
            As2[0][(ak2 + 7) * HSTR + arow] = h2u(__floats2half2_rn(av3.z, av3.w));
        } else {
            As2[0][(ak2 + 0) * HSTR + arow] = au0.x;
            As2[0][(ak2 + 1) * HSTR + arow] = au0.y;
            As2[0][(ak2 + 2) * HSTR + arow] = au0.z;
            As2[0][(ak2 + 3) * HSTR + arow] = au0.w;
            As2[0][(ak2 + 4) * HSTR + arow] = au1.x;
            As2[0][(ak2 + 5) * HSTR + arow] = au1.y;
            As2[0][(ak2 + 6) * HSTR + arow] = au1.z;
            As2[0][(ak2 + 7) * HSTR + arow] = au1.w;
        }
        Bs2[0][(ak2 + 0) * HSTR + arow] = h2u(__floats2half2_rn(bv0.x, bv0.y));
        Bs2[0][(ak2 + 1) * HSTR + arow] = h2u(__floats2half2_rn(bv0.z, bv0.w));
        Bs2[0][(ak2 + 2) * HSTR + arow] = h2u(__floats2half2_rn(bv1.x, bv1.y));
        Bs2[0][(ak2 + 3) * HSTR + arow] = h2u(__floats2half2_rn(bv1.z, bv1.w));
        Bs2[0][(ak2 + 4) * HSTR + arow] = h2u(__floats2half2_rn(bv2.x, bv2.y));
        Bs2[0][(ak2 + 5) * HSTR + arow] = h2u(__floats2half2_rn(bv2.z, bv2.w));
        Bs2[0][(ak2 + 6) * HSTR + arow] = h2u(__floats2half2_rn(bv3.x, bv3.y));
        Bs2[0][(ak2 + 7) * HSTR + arow] = h2u(__floats2half2_rn(bv3.z, bv3.w));
    }
    __syncthreads();

#pragma unroll 1
    for (int i = 0; i < niter; ++i) {
        const int pb = i & 1;
        if (i + 1 < niter) {
            const int k0 = (i + 1) * GBK;
            if (AMODE == 0) {
                av0 = *reinterpret_cast<const float4*>(Af + aoff + k0 + ak);
                av1 = *reinterpret_cast<const float4*>(Af + aoff + k0 + ak + 4);
                av2 = *reinterpret_cast<const float4*>(Af + aoff + k0 + ak + 8);
                av3 = *reinterpret_cast<const float4*>(Af + aoff + k0 + ak + 12);
            } else {
                au0 = *reinterpret_cast<const uint4*>(Ah + aoff + k0 + ak);
                au1 = *reinterpret_cast<const uint4*>(Ah + aoff + k0 + ak + 8);
            }
            bv0 = *reinterpret_cast<const float4*>(wrow + k0 + ak);
            bv1 = *reinterpret_cast<const float4*>(wrow + k0 + ak + 4);
            bv2 = *reinterpret_cast<const float4*>(wrow + k0 + ak + 8);
            bv3 = *reinterpret_cast<const float4*>(wrow + k0 + ak + 12);
        }

        // compute the 2 k16 sub-tiles from buf pb
#pragma unroll
        for (int kk = 0; kk < 16; kk += 8) {
            unsigned af[4][4], bf[4][2];
#pragma unroll
            for (int mt = 0; mt < 4; ++mt) {
                int m0 = wm * 64 + mt * 16;
                af[mt][0] = As2[pb][(kk + tig) * HSTR + m0 + g];
                af[mt][1] = As2[pb][(kk + tig) * HSTR + m0 + g + 8];
                af[mt][2] = As2[pb][(kk + tig + 4) * HSTR + m0 + g];
                af[mt][3] = As2[pb][(kk + tig + 4) * HSTR + m0 + g + 8];
            }
#pragma unroll
            for (int nt = 0; nt < 4; ++nt) {
                int n0 = wn * 32 + nt * 8;
                bf[nt][0] = Bs2[pb][(kk + tig) * HSTR + n0 + g];
                bf[nt][1] = Bs2[pb][(kk + tig + 4) * HSTR + n0 + g];
            }
#pragma unroll
            for (int mt = 0; mt < 4; ++mt)
#pragma unroll
                for (int nt = 0; nt < 4; ++nt)
                    mma_f16(c[mt][nt], af[mt], bf[nt]);
        }

        if (i + 1 < niter) {
            const int nb = pb ^ 1;
            if (AMODE == 0) {
                As2[nb][(ak2 + 0) * HSTR + arow] = h2u(__floats2half2_rn(av0.x, av0.y));
                As2[nb][(ak2 + 1) * HSTR + arow] = h2u(__floats2half2_rn(av0.z, av0.w));
                As2[nb][(ak2 + 2) * HSTR + arow] = h2u(__floats2half2_rn(av1.x, av1.y));
                As2[nb][(ak2 + 3) * HSTR + arow] = h2u(__floats2half2_rn(av1.z, av1.w));
                As2[nb][(ak2 + 4) * HSTR + arow] = h2u(__floats2half2_rn(av2.x, av2.y));
                As2[nb][(ak2 + 5) * HSTR + arow] = h2u(__floats2half2_rn(av2.z, av2.w));
                As2[nb][(ak2 + 6) * HSTR + arow] = h2u(__floats2half2_rn(av3.x, av3.y));
                As2[nb][(ak2 + 7) * HSTR + arow] = h2u(__floats2half2_rn(av3.z, av3.w));
            } else {
                As2[nb][(ak2 + 0) * HSTR + arow] = au0.x;
                As2[nb][(ak2 + 1) * HSTR + arow] = au0.y;
                As2[nb][(ak2 + 2) * HSTR + arow] = au0.z;
                As2[nb][(ak2 + 3) * HSTR + arow] = au0.w;
                As2[nb][(ak2 + 4) * HSTR + arow] = au1.x;
                As2[nb][(ak2 + 5) * HSTR + arow] = au1.y;
                As2[nb][(ak2 + 6) * HSTR + arow] = au1.z;
                As2[nb][(ak2 + 7) * HSTR + arow] = au1.w;
            }
            Bs2[nb][(ak2 + 0) * HSTR + arow] = h2u(__floats2half2_rn(bv0.x, bv0.y));
            Bs2[nb][(ak2 + 1) * HSTR + arow] = h2u(__floats2half2_rn(bv0.z, bv0.w));
            Bs2[nb][(ak2 + 2) * HSTR + arow] = h2u(__floats2half2_rn(bv1.x, bv1.y));
            Bs2[nb][(ak2 + 3) * HSTR + arow] = h2u(__floats2half2_rn(bv1.z, bv1.w));
            Bs2[nb][(ak2 + 4) * HSTR + arow] = h2u(__floats2half2_rn(bv2.x, bv2.y));
            Bs2[nb][(ak2 + 5) * HSTR + arow] = h2u(__floats2half2_rn(bv2.z, bv2.w));
            Bs2[nb][(ak2 + 6) * HSTR + arow] = h2u(__floats2half2_rn(bv3.x, bv3.y));
            Bs2[nb][(ak2 + 7) * HSTR + arow] = h2u(__floats2half2_rn(bv3.z, bv3.w));
        }
        __syncthreads();
    }

    // epilogue: D(row,col) with bias
#pragma unroll
    for (int mt = 0; mt < 4; ++mt) {
#pragma unroll
        for (int nt = 0; nt < 4; ++nt) {
            int r  = row0 + wm * 64 + mt * 16 + g;
            int cb = wn * 32 + nt * 8 + 2 * tig;
            int col = col0 + cb;
            float2 v0, v1;
            v0.x = c[mt][nt][0] + bias[cb];
            v0.y = c[mt][nt][1] + bias[cb + 1];
            v1.x = c[mt][nt][2] + bias[cb];
            v1.y = c[mt][nt][3] + bias[cb + 1];
            *reinterpret_cast<float2*>(&g_XP[(size_t)r * 1024 + col]) = v0;
            *reinterpret_cast<float2*>(&g_XP[(size_t)(r + 8) * 1024 + col]) = v1;
        }
    }
}

// ---------------------------------------------------------------------------
// LSTM recurrence: one block per (batch, dir). 512 threads = 16 warps.
// Warp w, lane l: hidden unit u = w*8 + (l&7), gate = l>>3.
// Weights in registers (fp16); h double-buffered in SMEM; tanh.approx
// activations applied pre-shfl; 4 independent half2 chains; pointer marching.
// layer 0 writes g_H0h (half); layer 1 writes g_H1 (float).
// ---------------------------------------------------------------------------
__global__ __launch_bounds__(512) void lstm_kernel(
    const float* __restrict__ whh_fwd, const float* __restrict__ whh_rev, int layer)
{
    __shared__ uint4 hbuf4[2][16];   // 2 x 128 halves

    const int b   = blockIdx.x >> 1;
    const int dir = blockIdx.x & 1;
    const float* whh = dir ? whh_rev : whh_fwd;

    const int lane = threadIdx.x & 31;
    const int wid  = threadIdx.x >> 5;
    const int u    = wid * 8 + (lane & 7);
    const int gate = lane >> 3;
    const int wrow_idx = gate * 128 + u;

    // weights -> registers (fp16)
    __half2 W[64];
    {
        const float4* wr4 = reinterpret_cast<const float4*>(whh + (size_t)wrow_idx * 128);
#pragma unroll
        for (int i = 0; i < 32; ++i) {
            float4 f = wr4[i];
            W[2 * i]     = __floats2half2_rn(f.x, f.y);
            W[2 * i + 1] = __floats2half2_rn(f.z, f.w);
        }
    }
    if (threadIdx.x < 16) hbuf4[0][threadIdx.x] = make_uint4(0u, 0u, 0u, 0u);
    float cst = 0.f;
    __syncthreads();

    const long xstride = dir ? -(long)(BB * 1024) : (long)(BB * 1024);
    const long hstride = dir ? -(long)(BB * 256)  : (long)(BB * 256);
    const size_t hbase = (size_t)(dir ? (TT - 1) : 0) * (BB * 256)
                       + (size_t)b * 256 + dir * 128 + u;
    const float* xp_p = g_XP + (size_t)(dir ? (TT - 1) : 0) * (BB * 1024)
                             + (size_t)b * 1024 + dir * 512 + wrow_idx;
    __half* houth_p = g_H0h + hbase;
    float*  houtf_p = g_H1 + hbase;

    float xp = *xp_p;

    for (int t = 0; t < TT; ++t) {
        // prefetch next step's xp (clamped pointer on last step)
        const float* pf = xp_p + ((t < TT - 1) ? xstride : 0);
        float xpn = *pf;

        const uint4* hb = hbuf4[t & 1];
        __half2 s0 = __floats2half2_rn(0.f, 0.f);
        __half2 s1 = s0, s2 = s0, s3 = s0;
#pragma unroll
        for (int k = 0; k < 4; ++k) {
            uint4 ha = hb[4 * k];
            uint4 hc = hb[4 * k + 1];
            uint4 hd = hb[4 * k + 2];
            uint4 he = hb[4 * k + 3];
            s0 = __hfma2(W[16 * k + 0],  u2h2(ha.x), s0);
            s1 = __hfma2(W[16 * k + 1],  u2h2(ha.y), s1);
            s2 = __hfma2(W[16 * k + 2],  u2h2(ha.z), s2);
            s3 = __hfma2(W[16 * k + 3],  u2h2(ha.w), s3);
            s0 = __hfma2(W[16 * k + 4],  u2h2(hc.x), s0);
            s1 = __hfma2(W[16 * k + 5],  u2h2(hc.y), s1);
            s2 = __hfma2(W[16 * k + 6],  u2h2(hc.z), s2);
            s3 = __hfma2(W[16 * k + 7],  u2h2(hc.w), s3);
            s0 = __hfma2(W[16 * k + 8],  u2h2(hd.x), s0);
            s1 = __hfma2(W[16 * k + 9],  u2h2(hd.y), s1);
            s2 = __hfma2(W[16 * k + 10], u2h2(hd.z), s2);
            s3 = __hfma2(W[16 * k + 11], u2h2(hd.w), s3);
            s0 = __hfma2(W[16 * k + 12], u2h2(he.x), s0);
            s1 = __hfma2(W[16 * k + 13], u2h2(he.y), s1);
            s2 = __hfma2(W[16 * k + 14], u2h2(he.z), s2);
            s3 = __hfma2(W[16 * k + 15], u2h2(he.w), s3);
        }
        __half2 sh = __hadd2(__hadd2(s0, s1), __hadd2(s2, s3));
        float2 f2 = __half22float2(sh);
        const float gval = f2.x + f2.y + xp;

        // activation by owning lane: tanh for gate 2, sigmoid (via tanh) else
        const float act = (gate == 2) ? tanha(gval) : sigt(gval);

        const int src = lane & 7;
        float iv = __shfl_sync(0xffffffffu, act, src);
        float fv = __shfl_sync(0xffffffffu, act, src + 8);
        float gv = __shfl_sync(0xffffffffu, act, src + 16);
        float ov = __shfl_sync(0xffffffffu, act, src + 24);

        if (lane < 8) {
            float cn = fv * cst + iv * gv;
            cst = cn;
            float hn = ov * tanha(cn);
            reinterpret_cast<__half*>(&hbuf4[(t & 1) ^ 1][0])[u] = __float2half_rn(hn);
            if (layer == 0) *houth_p = __float2half_rn(hn);
            else            *houtf_p = hn;
        }
        xp = xpn;
        xp_p += xstride;
        houth_p += hstride;
        houtf_p += hstride;
        __syncthreads();
    }
}

// ---------------------------------------------------------------------------
// Emissions: EM[r][n] = H1[r][:] . linear_w[n][:] + linear_b[n], n padded to 16
// ---------------------------------------------------------------------------
__global__ __launch_bounds__(256) void emis_kernel(
    const float* __restrict__ lw, const float* __restrict__ lb)
{
    const int r = blockIdx.x * 16 + (threadIdx.x >> 4);
    const int n = threadIdx.x & 15;
    float acc = 0.f;
    if (n < KK) {
        const float4* h4 = reinterpret_cast<const float4*>(&g_H1[(size_t)r * 256]);
        const float4* w4 = reinterpret_cast<const float4*>(lw + (size_t)n * 256);
#pragma unroll 8
        for (int k = 0; k < 64; ++k) {
            float4 a = h4[k], w = w4[k];
            acc += a.x * w.x + a.y * w.y + a.z * w.z + a.w * w.w;
        }
        acc += lb[n];
    }
    g_EM[(size_t)r * 16 + n] = acc;
}

// ---------------------------------------------------------------------------
// CRF: one block per batch.
// ---------------------------------------------------------------------------
__global__ __launch_bounds__(256) void crf_kernel(
    const int* __restrict__ tags, const void* __restrict__ maskraw,
    const float* __restrict__ start_t, const float* __restrict__ end_t,
    const float* __restrict__ trans)
{
    __shared__ float ems[TT * 12];
    __shared__ float redf[256];
    __shared__ int   redi[256];
    __shared__ unsigned char maskb[TT];
    __shared__ float s_num;

    const int b = blockIdx.x;
    const int tid = threadIdx.x;

    {
        const unsigned char* mc = reinterpret_cast<const unsigned char*>(maskraw);
        const bool bytewise = (mc[1] != 0);
        const int* mi = reinterpret_cast<const int*>(maskraw);
        for (int t = tid; t < TT; t += 256) {
            maskb[t] = bytewise ? (mc[(size_t)b * TT + t] != 0)
                                : (mi[(size_t)b * TT + t] != 0);
        }
    }
    for (int base = tid; base < TT * 16; base += 256) {
        int t = base >> 4, j = base & 15;
        if (j < KK) ems[t * 12 + j] = g_EM[((size_t)t * BB + b) * 16 + j];
    }
    __syncthreads();

    float part = 0.f;
    int   cnt  = 0;
    for (int t = tid; t < TT; t += 256) cnt += maskb[t] ? 1 : 0;
    for (int t = 1 + tid; t < TT; t += 256) {
        if (maskb[t]) {
            int tp = tags[(size_t)b * TT + t - 1];
            int tc = tags[(size_t)b * TT + t];
            part += trans[tp * KK + tc] + ems[t * 12 + tc];
        }
    }
    redf[tid] = part; redi[tid] = cnt;
    __syncthreads();
    for (int s = 128; s > 0; s >>= 1) {
        if (tid < s) { redf[tid] += redf[tid + s]; redi[tid] += redi[tid + s]; }
        __syncthreads();
    }
    if (tid == 0) {
        int t0 = tags[(size_t)b * TT];
        int seqEnd = redi[0] - 1;
        s_num = start_t[t0] + ems[t0] + redf[0]
              + end_t[tags[(size_t)b * TT + seqEnd]];
    }
    __syncthreads();

    if (tid < 32) {
        const int lane = tid;
        float tcol[KK];
        if (lane < KK) {
#pragma unroll
            for (int i = 0; i < KK; i++) tcol[i] = trans[i * KK + lane];
        } else {
#pragma unroll
            for (int i = 0; i < KK; i++) tcol[i] = 0.f;
        }
        float score = (lane < KK) ? (start_t[lane] + ems[lane]) : -1e30f;

        for (int t = 1; t < TT; ++t) {
            if (maskb[t]) {
                float vi[KK];
                float m = -1e30f;
#pragma unroll
                for (int i = 0; i < KK; i++) {
                    float si = __shfl_sync(0xffffffffu, score, i);
                    vi[i] = si + tcol[i];
                    m = fmaxf(m, vi[i]);
                }
                float ssum = 0.f;
#pragma unroll
                for (int i = 0; i < KK; i++) ssum += __expf(vi[i] - m);
                float nxt = m + __logf(ssum) + ems[t * 12 + lane];
                if (lane < KK) score = nxt;
            }
        }
        float v = (lane < KK) ? (score + end_t[lane]) : -1e30f;
        float m = v;
#pragma unroll
        for (int off = 16; off > 0; off >>= 1)
            m = fmaxf(m, __shfl_xor_sync(0xffffffffu, m, off));
        float e = __expf(v - m);
#pragma unroll
        for (int off = 16; off > 0; off >>= 1)
            e += __shfl_xor_sync(0xffffffffu, e, off);
        float den = m + __logf(e);
        if (lane == 0) g_ND[b] = s_num - den;
    }
}

__global__ void finish_kernel(float* __restrict__ out, int out_n)
{
    __shared__ float s[64];
    int tid = threadIdx.x;
    s[tid] = g_ND[tid];
    __syncthreads();
    for (int st = 32; st > 0; st >>= 1) {
        if (tid < st) s[tid] += s[tid + st];
        __syncthreads();
    }
    if (tid == 0) out[0] = -s[0] / 64.f;
    if (tid > 0 && tid < out_n) out[tid] = 0.f;
}

// ---------------------------------------------------------------------------
extern "C" void kernel_launch(void* const* d_in, const int* in_sizes, int n_in,
                              void* d_out, int out_size)
{
    const float* embeds    = (const float*)d_in[0];
    const int*   tags      = (const int*)d_in[1];
    const void*  mask      = d_in[2];
    const float* w_ih_l0   = (const float*)d_in[3];
    const float* w_hh_l0   = (const float*)d_in[4];
    const float* b_ih_l0   = (const float*)d_in[5];
    const float* b_hh_l0   = (const float*)d_in[6];
    const float* w_ih_l0r  = (const float*)d_in[7];
    const float* w_hh_l0r  = (const float*)d_in[8];
    const float* b_ih_l0r  = (const float*)d_in[9];
    const float* b_hh_l0r  = (const float*)d_in[10];
    const float* w_ih_l1   = (const float*)d_in[11];
    const float* w_hh_l1   = (const float*)d_in[12];
    const float* b_ih_l1   = (const float*)d_in[13];
    const float* b_hh_l1   = (const float*)d_in[14];
    const float* w_ih_l1r  = (const float*)d_in[15];
    const float* w_hh_l1r  = (const float*)d_in[16];
    const float* b_ih_l1r  = (const float*)d_in[17];
    const float* b_hh_l1r  = (const float*)d_in[18];
    const float* linear_w  = (const float*)d_in[19];
    const float* linear_b  = (const float*)d_in[20];
    const float* start_tr  = (const float*)d_in[21];
    const float* end_tr    = (const float*)d_in[22];
    const float* trans     = (const float*)d_in[23];
    (void)in_sizes; (void)n_in;

    dim3 ggrid(8, 256);   // N/128 x M/128

    // layer 0
    gemm_tc<0><<<ggrid, 256>>>(embeds, 768,
                               w_ih_l0, w_ih_l0r, b_ih_l0, b_hh_l0, b_ih_l0r, b_hh_l0r);
    lstm_kernel<<<128, 512>>>(w_hh_l0, w_hh_l0r, 0);

    // layer 1 (A = g_H0h, fp16)
    gemm_tc<1><<<ggrid, 256>>>(nullptr, 256,
                               w_ih_l1, w_ih_l1r, b_ih_l1, b_hh_l1, b_ih_l1r, b_hh_l1r);
    lstm_kernel<<<128, 512>>>(w_hh_l1, w_hh_l1r, 1);

    // emissions + CRF
    emis_kernel<<<2048, 256>>>(linear_w, linear_b);
    crf_kernel<<<64, 256>>>(tags, mask, start_tr, end_tr, trans);
    finish_kernel<<<1, 64>>>((float*)d_out, out_size);
}

// round 6
// speedup vs baseline: 2.6603x; 1.0341x over previous
#include <cuda_runtime.h>
#include <cuda_fp16.h>
#include <cuda_bf16.h>

// Problem constants
#define BB 64
#define TT 512
#define EE 768
#define HH 128      // hidden per direction
#define KK 11

// ---------------------------------------------------------------------------
// Scratch (device globals; no dynamic allocation allowed)
// ---------------------------------------------------------------------------
__device__ __half g_XPh[(size_t)TT * BB * 1024];  // gate x-contributions (fp16)
__device__ __half g_H0h[(size_t)TT * BB * 256];   // layer0 h (fp16, gemm1 A)
__device__ __half g_H1h[(size_t)TT * BB * 256];   // layer1 h (fp16, emis input)
__device__ float  g_EM[(size_t)TT * BB * 16];     // emissions padded to 16
__device__ float  g_ND[BB];                       // num - den per batch

__device__ __forceinline__ float tanha(float x) {
    float r; asm("tanh.approx.f32 %0, %1;" : "=f"(r) : "f"(x)); return r;
}
__device__ __forceinline__ float sigt(float x) {   // sigmoid via tanh
    return fmaf(0.5f, tanha(0.5f * x), 0.5f);
}
__device__ __forceinline__ __half2 u2h2(unsigned int u) {
    __half2 r; *reinterpret_cast<unsigned int*>(&r) = u; return r;
}
__device__ __forceinline__ unsigned h2u(__half2 h) {
    return *reinterpret_cast<unsigned*>(&h);
}
__device__ __forceinline__ void mma_f16(float* d, const unsigned* a, const unsigned* b) {
    asm volatile(
        "mma.sync.aligned.m16n8k16.row.col.f32.f16.f16.f32 "
        "{%0,%1,%2,%3},{%4,%5,%6,%7},{%8,%9},{%0,%1,%2,%3};"
        : "+f"(d[0]), "+f"(d[1]), "+f"(d[2]), "+f"(d[3])
        : "r"(a[0]), "r"(a[1]), "r"(a[2]), "r"(a[3]), "r"(b[0]), "r"(b[1]));
}

// ---------------------------------------------------------------------------
// fp16 tensor-core GEMM (fp32 accum): XPh[r][n] = A[r][:].W[n][:] + bias[n]
//   r = t*64+b;  AMODE 0: A=embeds (B,T,E) fp32, row r -> ((r&63)*512+(r>>6))*768
//                AMODE 1: A=g_H0h (row-major 256, fp16)
//   n<512 -> W0/bias0 (fwd), else W1/bias1 (rev)
// Tile BM=128, BN=128, BK=16; 8 warps (2m x 4n), warp tile 64x32.
// SMEM: half2 k2-major [k2][m], stride 136 (conflict-free frags), double buffer.
// ---------------------------------------------------------------------------
#define GBK 16
#define HSTR 136

template<int AMODE>
__global__ __launch_bounds__(256) void gemm_tc(
    const float* __restrict__ Aext, int Kdim,
    const float* __restrict__ W0, const float* __restrict__ W1,
    const float* __restrict__ bi0, const float* __restrict__ bh0,
    const float* __restrict__ bi1, const float* __restrict__ bh1)
{
    __shared__ unsigned As2[2][8 * HSTR];
    __shared__ unsigned Bs2[2][8 * HSTR];
    __shared__ float bias[128];

    const int tid  = threadIdx.x;
    const int lane = tid & 31, wid = tid >> 5;
    const int wm = wid >> 2, wn = wid & 3;        // 2 x 4 warp grid
    const int g = lane >> 2, tig = lane & 3;
    const int row0 = blockIdx.y * 128;
    const int col0 = blockIdx.x * 128;

    if (tid < 128) {
        int n = col0 + tid;
        bias[tid] = (n < 512) ? (bi0[n] + bh0[n]) : (bi1[n - 512] + bh1[n - 512]);
    }

    // global load mapping: per thread 8 values of A, 8 of B per 16-k tile
    const int arow = tid >> 1;             // 0..127
    const int ak   = (tid & 1) * 8;        // 0 or 8
    const int ak2  = ak >> 1;              // 0 or 4
    size_t aoff;
    {
        int r = row0 + arow;
        aoff = (AMODE == 0) ? ((size_t)(r & 63) * 512 + (size_t)(r >> 6)) * 768
                            : (size_t)r * 256;
    }
    const float* Af = Aext;
    const __half* Ah = g_H0h;
    const int nG = col0 + arow;
    const float* wrow = (nG < 512) ? (W0 + (size_t)nG * Kdim)
                                   : (W1 + (size_t)(nG - 512) * Kdim);

    float c[4][4][4];
#pragma unroll
    for (int i = 0; i < 4; i++)
#pragma unroll
        for (int j = 0; j < 4; j++)
#pragma unroll
            for (int q = 0; q < 4; q++) c[i][j][q] = 0.f;

    const int niter = Kdim / GBK;

    float4 av0, av1;     // AMODE 0
    uint4  au0;          // AMODE 1
    float4 bv0, bv1;

    // ---- prologue: tile 0 -> buf 0
    if (AMODE == 0) {
        av0 = *reinterpret_cast<const float4*>(Af + aoff + ak);
        av1 = *reinterpret_cast<const float4*>(Af + aoff + ak + 4);
    } else {
        au0 = *reinterpret_cast<const uint4*>(Ah + aoff + ak);
    }
    bv0 = *reinterpret_cast<const float4*>(wrow + ak);
    bv1 = *reinterpret_cast<const float4*>(wrow + ak + 4);

    if (AMODE == 0) {
        As2[0][(ak2 + 0) * HSTR + arow] = h2u(__floats2half2_rn(av0.x, av0.y));
        As2[0][(ak2 + 1) * HSTR + arow] = h2u(__floats2half2_rn(av0.z, av0.w));
        As2[0][(ak2 + 2) * HSTR + arow] = h2u(__floats2half2_rn(av1.x, av1.y));
        As2[0][(ak2 + 3) * HSTR + arow] = h2u(__floats2half2_rn(av1.z, av1.w));
    } else {
        As2[0][(ak2 + 0) * HSTR + arow] = au0.x;
        As2[0][(ak2 + 1) * HSTR + arow] = au0.y;
        As2[0][(ak2 + 2) * HSTR + arow] = au0.z;
        As2[0][(ak2 + 3) * HSTR + arow] = au0.w;
    }
    Bs2[0][(ak2 + 0) * HSTR + arow] = h2u(__floats2half2_rn(bv0.x, bv0.y));
    Bs2[0][(ak2 + 1) * HSTR + arow] = h2u(__floats2half2_rn(bv0.z, bv0.w));
    Bs2[0][(ak2 + 2) * HSTR + arow] = h2u(__floats2half2_rn(bv1.x, bv1.y));
    Bs2[0][(ak2 + 3) * HSTR + arow] = h2u(__floats2half2_rn(bv1.z, bv1.w));
    __syncthreads();

#pragma unroll 1
    for (int i = 0; i < niter; ++i) {
        const int pb = i & 1;
        if (i + 1 < niter) {
            const int k0 = (i + 1) * GBK;
            if (AMODE == 0) {
                av0 = *reinterpret_cast<const float4*>(Af + aoff + k0 + ak);
                av1 = *reinterpret_cast<const float4*>(Af + aoff + k0 + ak + 4);
            } else {
                au0 = *reinterpret_cast<const uint4*>(Ah + aoff + k0 + ak);
            }
            bv0 = *reinterpret_cast<const float4*>(wrow + k0 + ak);
            bv1 = *reinterpret_cast<const float4*>(wrow + k0 + ak + 4);
        }

        // compute tile i from buf pb
        {
            unsigned af[4][4], bf[4][2];
#pragma unroll
            for (int mt = 0; mt < 4; ++mt) {
                int m0 = wm * 64 + mt * 16;
                af[mt][0] = As2[pb][tig * HSTR + m0 + g];
                af[mt][1] = As2[pb][tig * HSTR + m0 + g + 8];
                af[mt][2] = As2[pb][(tig + 4) * HSTR + m0 + g];
                af[mt][3] = As2[pb][(tig + 4) * HSTR + m0 + g + 8];
            }
#pragma unroll
            for (int nt = 0; nt < 4; ++nt) {
                int n0 = wn * 32 + nt * 8;
                bf[nt][0] = Bs2[pb][tig * HSTR + n0 + g];
                bf[nt][1] = Bs2[pb][(tig + 4) * HSTR + n0 + g];
            }
#pragma unroll
            for (int mt = 0; mt < 4; ++mt)
#pragma unroll
                for (int nt = 0; nt < 4; ++nt)
                    mma_f16(c[mt][nt], af[mt], bf[nt]);
        }

        if (i + 1 < niter) {
            const int nb = pb ^ 1;
            if (AMODE == 0) {
                As2[nb][(ak2 + 0) * HSTR + arow] = h2u(__floats2half2_rn(av0.x, av0.y));
                As2[nb][(ak2 + 1) * HSTR + arow] = h2u(__floats2half2_rn(av0.z, av0.w));
                As2[nb][(ak2 + 2) * HSTR + arow] = h2u(__floats2half2_rn(av1.x, av1.y));
                As2[nb][(ak2 + 3) * HSTR + arow] = h2u(__floats2half2_rn(av1.z, av1.w));
            } else {
                As2[nb][(ak2 + 0) * HSTR + arow] = au0.x;
                As2[nb][(ak2 + 1) * HSTR + arow] = au0.y;
                As2[nb][(ak2 + 2) * HSTR + arow] = au0.z;
                As2[nb][(ak2 + 3) * HSTR + arow] = au0.w;
            }
            Bs2[nb][(ak2 + 0) * HSTR + arow] = h2u(__floats2half2_rn(bv0.x, bv0.y));
            Bs2[nb][(ak2 + 1) * HSTR + arow] = h2u(__floats2half2_rn(bv0.z, bv0.w));
            Bs2[nb][(ak2 + 2) * HSTR + arow] = h2u(__floats2half2_rn(bv1.x, bv1.y));
            Bs2[nb][(ak2 + 3) * HSTR + arow] = h2u(__floats2half2_rn(bv1.z, bv1.w));
        }
        __syncthreads();
    }

    // epilogue: XPh(row,col) = c + bias, packed half2
#pragma unroll
    for (int mt = 0; mt < 4; ++mt) {
#pragma unroll
        for (int nt = 0; nt < 4; ++nt) {
            int r  = row0 + wm * 64 + mt * 16 + g;
            int cb = wn * 32 + nt * 8 + 2 * tig;
            int col = col0 + cb;
            unsigned p0 = h2u(__floats2half2_rn(c[mt][nt][0] + bias[cb],
                                                c[mt][nt][1] + bias[cb + 1]));
            unsigned p1 = h2u(__floats2half2_rn(c[mt][nt][2] + bias[cb],
                                                c[mt][nt][3] + bias[cb + 1]));
            *reinterpret_cast<unsigned*>(&g_XPh[(size_t)r * 1024 + col]) = p0;
            *reinterpret_cast<unsigned*>(&g_XPh[(size_t)(r + 8) * 1024 + col]) = p1;
        }
    }
}

// ---------------------------------------------------------------------------
// LSTM recurrence: one block per (batch, dir). 512 threads = 16 warps.
// Warp w, lane l: hidden unit u = w*8 + (l&7), gate = l>>3.
// Weights in registers (fp16); h double-buffered in SMEM; tanh.approx
// activations applied pre-shfl; 4 independent half2 chains; pointer marching.
// xp read as fp16; h written to g_H0h / g_H1h (fp16).
// ---------------------------------------------------------------------------
__global__ __launch_bounds__(512) void lstm_kernel(
    const float* __restrict__ whh_fwd, const float* __restrict__ whh_rev, int layer)
{
    __shared__ uint4 hbuf4[2][16];   // 2 x 128 halves

    const int b   = blockIdx.x >> 1;
    const int dir = blockIdx.x & 1;
    const float* whh = dir ? whh_rev : whh_fwd;

    const int lane = threadIdx.x & 31;
    const int wid  = threadIdx.x >> 5;
    const int u    = wid * 8 + (lane & 7);
    const int gate = lane >> 3;
    const int wrow_idx = gate * 128 + u;

    // weights -> registers (fp16)
    __half2 W[64];
    {
        const float4* wr4 = reinterpret_cast<const float4*>(whh + (size_t)wrow_idx * 128);
#pragma unroll
        for (int i = 0; i < 32; ++i) {
            float4 f = wr4[i];
            W[2 * i]     = __floats2half2_rn(f.x, f.y);
            W[2 * i + 1] = __floats2half2_rn(f.z, f.w);
        }
    }
    if (threadIdx.x < 16) hbuf4[0][threadIdx.x] = make_uint4(0u, 0u, 0u, 0u);
    float cst = 0.f;
    __syncthreads();

    const long xstride = dir ? -(long)(BB * 1024) : (long)(BB * 1024);
    const long hstride = dir ? -(long)(BB * 256)  : (long)(BB * 256);
    const size_t hbase = (size_t)(dir ? (TT - 1) : 0) * (BB * 256)
                       + (size_t)b * 256 + dir * 128 + u;
    const __half* xp_p = g_XPh + (size_t)(dir ? (TT - 1) : 0) * (BB * 1024)
                               + (size_t)b * 1024 + dir * 512 + wrow_idx;
    __half* hout_p = (layer ? g_H1h : g_H0h) + hbase;

    float xp = __half2float(*xp_p);

    for (int t = 0; t < TT; ++t) {
        // prefetch next step's xp (clamped pointer on last step)
        const __half* pf = xp_p + ((t < TT - 1) ? xstride : 0);
        float xpn = __half2float(*pf);

        const uint4* hb = hbuf4[t & 1];
        __half2 s0 = __floats2half2_rn(0.f, 0.f);
        __half2 s1 = s0, s2 = s0, s3 = s0;
#pragma unroll
        for (int k = 0; k < 4; ++k) {
            uint4 ha = hb[4 * k];
            uint4 hc = hb[4 * k + 1];
            uint4 hd = hb[4 * k + 2];
            uint4 he = hb[4 * k + 3];
            s0 = __hfma2(W[16 * k + 0],  u2h2(ha.x), s0);
            s1 = __hfma2(W[16 * k + 1],  u2h2(ha.y), s1);
            s2 = __hfma2(W[16 * k + 2],  u2h2(ha.z), s2);
            s3 = __hfma2(W[16 * k + 3],  u2h2(ha.w), s3);
            s0 = __hfma2(W[16 * k + 4],  u2h2(hc.x), s0);
            s1 = __hfma2(W[16 * k + 5],  u2h2(hc.y), s1);
            s2 = __hfma2(W[16 * k + 6],  u2h2(hc.z), s2);
            s3 = __hfma2(W[16 * k + 7],  u2h2(hc.w), s3);
            s0 = __hfma2(W[16 * k + 8],  u2h2(hd.x), s0);
            s1 = __hfma2(W[16 * k + 9],  u2h2(hd.y), s1);
            s2 = __hfma2(W[16 * k + 10], u2h2(hd.z), s2);
            s3 = __hfma2(W[16 * k + 11], u2h2(hd.w), s3);
            s0 = __hfma2(W[16 * k + 12], u2h2(he.x), s0);
            s1 = __hfma2(W[16 * k + 13], u2h2(he.y), s1);
            s2 = __hfma2(W[16 * k + 14], u2h2(he.z), s2);
            s3 = __hfma2(W[16 * k + 15], u2h2(he.w), s3);
        }
        __half2 sh = __hadd2(__hadd2(s0, s1), __hadd2(s2, s3));
        float2 f2 = __half22float2(sh);
        const float gval = f2.x + f2.y + xp;

        // activation by owning lane: tanh for gate 2, sigmoid (via tanh) else
        const float act = (gate == 2) ? tanha(gval) : sigt(gval);

        const int src = lane & 7;
        float iv = __shfl_sync(0xffffffffu, act, src);
        float fv = __shfl_sync(0xffffffffu, act, src + 8);
        float gv = __shfl_sync(0xffffffffu, act, src + 16);
        float ov = __shfl_sync(0xffffffffu, act, src + 24);

        if (lane < 8) {
            float cn = fv * cst + iv * gv;
            cst = cn;
            float hn = ov * tanha(cn);
            __half hcvt = __float2half_rn(hn);
            reinterpret_cast<__half*>(&hbuf4[(t & 1) ^ 1][0])[u] = hcvt;
            *hout_p = hcvt;
        }
        xp = xpn;
        xp_p += xstride;
        hout_p += hstride;
        __syncthreads();
    }
}

// ---------------------------------------------------------------------------
// Emissions: EM[r][n] = H1h[r][:] . linear_w[n][:] + linear_b[n], n padded to 16
// ---------------------------------------------------------------------------
__global__ __launch_bounds__(256) void emis_kernel(
    const float* __restrict__ lw, const float* __restrict__ lb)
{
    const int r = blockIdx.x * 16 + (threadIdx.x >> 4);
    const int n = threadIdx.x & 15;
    float acc = 0.f;
    if (n < KK) {
        const uint4*  h4 = reinterpret_cast<const uint4*>(&g_H1h[(size_t)r * 256]);
        const float4* w4 = reinterpret_cast<const float4*>(lw + (size_t)n * 256);
#pragma unroll 8
        for (int k = 0; k < 32; ++k) {
            uint4 hv = h4[k];
            float4 w0 = w4[2 * k], w1 = w4[2 * k + 1];
            float2 a0 = __half22float2(u2h2(hv.x));
            float2 a1 = __half22float2(u2h2(hv.y));
            float2 a2 = __half22float2(u2h2(hv.z));
            float2 a3 = __half22float2(u2h2(hv.w));
            acc += a0.x * w0.x + a0.y * w0.y + a1.x * w0.z + a1.y * w0.w;
            acc += a2.x * w1.x + a2.y * w1.y + a3.x * w1.z + a3.y * w1.w;
        }
        acc += lb[n];
    }
    g_EM[(size_t)r * 16 + n] = acc;
}

// ---------------------------------------------------------------------------
// CRF: one block per batch.
// ---------------------------------------------------------------------------
__global__ __launch_bounds__(256) void crf_kernel(
    const int* __restrict__ tags, const void* __restrict__ maskraw,
    const float* __restrict__ start_t, const float* __restrict__ end_t,
    const float* __restrict__ trans)
{
    __shared__ float ems[TT * 12];
    __shared__ float redf[256];
    __shared__ int   redi[256];
    __shared__ unsigned char maskb[TT];
    __shared__ float s_num;

    const int b = blockIdx.x;
    const int tid = threadIdx.x;

    {
        const unsigned char* mc = reinterpret_cast<const unsigned char*>(maskraw);
        const bool bytewise = (mc[1] != 0);
        const int* mi = reinterpret_cast<const int*>(maskraw);
        for (int t = tid; t < TT; t += 256) {
            maskb[t] = bytewise ? (mc[(size_t)b * TT + t] != 0)
                                : (mi[(size_t)b * TT + t] != 0);
        }
    }
    for (int base = tid; base < TT * 16; base += 256) {
        int t = base >> 4, j = base & 15;
        if (j < KK) ems[t * 12 + j] = g_EM[((size_t)t * BB + b) * 16 + j];
    }
    __syncthreads();

    float part = 0.f;
    int   cnt  = 0;
    for (int t = tid; t < TT; t += 256) cnt += maskb[t] ? 1 : 0;
    for (int t = 1 + tid; t < TT; t += 256) {
        if (maskb[t]) {
            int tp = tags[(size_t)b * TT + t - 1];
            int tc = tags[(size_t)b * TT + t];
            part += trans[tp * KK + tc] + ems[t * 12 + tc];
        }
    }
    redf[tid] = part; redi[tid] = cnt;
    __syncthreads();
    for (int s = 128; s > 0; s >>= 1) {
        if (tid < s) { redf[tid] += redf[tid + s]; redi[tid] += redi[tid + s]; }
        __syncthreads();
    }
    if (tid == 0) {
        int t0 = tags[(size_t)b * TT];
        int seqEnd = redi[0] - 1;
        s_num = start_t[t0] + ems[t0] + redf[0]
              + end_t[tags[(size_t)b * TT + seqEnd]];
    }
    __syncthreads();

    if (tid < 32) {
        const int lane = tid;
        float tcol[KK];
        if (lane < KK) {
#pragma unroll
            for (int i = 0; i < KK; i++) tcol[i] = trans[i * KK + lane];
        } else {
#pragma unroll
            for (int i = 0; i < KK; i++) tcol[i] = 0.f;
        }
        float score = (lane < KK) ? (start_t[lane] + ems[lane]) : -1e30f;

        for (int t = 1; t < TT; ++t) {
            if (maskb[t]) {
                float vi[KK];
                float m = -1e30f;
#pragma unroll
                for (int i = 0; i < KK; i++) {
                    float si = __shfl_sync(0xffffffffu, score, i);
                    vi[i] = si + tcol[i];
                    m = fmaxf(m, vi[i]);
                }
                float ssum = 0.f;
#pragma unroll
                for (int i = 0; i < KK; i++) ssum += __expf(vi[i] - m);
                float nxt = m + __logf(ssum) + ems[t * 12 + lane];
                if (lane < KK) score = nxt;
            }
        }
        float v = (lane < KK) ? (score + end_t[lane]) : -1e30f;
        float m = v;
#pragma unroll
        for (int off = 16; off > 0; off >>= 1)
            m = fmaxf(m, __shfl_xor_sync(0xffffffffu, m, off));
        float e = __expf(v - m);
#pragma unroll
        for (int off = 16; off > 0; off >>= 1)
            e += __shfl_xor_sync(0xffffffffu, e, off);
        float den = m + __logf(e);
        if (lane == 0) g_ND[b] = s_num - den;
    }
}

__global__ void finish_kernel(float* __restrict__ out, int out_n)
{
    __shared__ float s[64];
    int tid = threadIdx.x;
    s[tid] = g_ND[tid];
    __syncthreads();
    for (int st = 32; st > 0; st >>= 1) {
        if (tid < st) s[tid] += s[tid + st];
        __syncthreads();
    }
    if (tid == 0) out[0] = -s[0] / 64.f;
    if (tid > 0 && tid < out_n) out[tid] = 0.f;
}

// ---------------------------------------------------------------------------
extern "C" void kernel_launch(void* const* d_in, const int* in_sizes, int n_in,
                              void* d_out, int out_size)
{
    const float* embeds    = (const float*)d_in[0];
    const int*   tags      = (const int*)d_in[1];
    const void*  mask      = d_in[2];
    const float* w_ih_l0   = (const float*)d_in[3];
    const float* w_hh_l0   = (const float*)d_in[4];
    const float* b_ih_l0   = (const float*)d_in[5];
    const float* b_hh_l0   = (const float*)d_in[6];
    const float* w_ih_l0r  = (const float*)d_in[7];
    const float* w_hh_l0r  = (const float*)d_in[8];
    const float* b_ih_l0r  = (const float*)d_in[9];
    const float* b_hh_l0r  = (const float*)d_in[10];
    const float* w_ih_l1   = (const float*)d_in[11];
    const float* w_hh_l1   = (const float*)d_in[12];
    const float* b_ih_l1   = (const float*)d_in[13];
    const float* b_hh_l1   = (const float*)d_in[14];
    const float* w_ih_l1r  = (const float*)d_in[15];
    const float* w_hh_l1r  = (const float*)d_in[16];
    const float* b_ih_l1r  = (const float*)d_in[17];
    const float* b_hh_l1r  = (const float*)d_in[18];
    const float* linear_w  = (const float*)d_in[19];
    const float* linear_b  = (const float*)d_in[20];
    const float* start_tr  = (const float*)d_in[21];
    const float* end_tr    = (const float*)d_in[22];
    const float* trans     = (const float*)d_in[23];
    (void)in_sizes; (void)n_in;

    dim3 ggrid(8, 256);   // N/128 x M/128

    // layer 0
    gemm_tc<0><<<ggrid, 256>>>(embeds, 768,
                               w_ih_l0, w_ih_l0r, b_ih_l0, b_hh_l0, b_ih_l0r, b_hh_l0r);
    lstm_kernel<<<128, 512>>>(w_hh_l0, w_hh_l0r, 0);

    // layer 1 (A = g_H0h, fp16)
    gemm_tc<1><<<ggrid, 256>>>(nullptr, 256,
                               w_ih_l1, w_ih_l1r, b_ih_l1, b_hh_l1, b_ih_l1r, b_hh_l1r);
    lstm_kernel<<<128, 512>>>(w_hh_l1, w_hh_l1r, 1);

    // emissions + CRF
    emis_kernel<<<2048, 256>>>(linear_w, linear_b);
    crf_kernel<<<64, 256>>>(tags, mask, start_tr, end_tr, trans);
    finish_kernel<<<1, 64>>>((float*)d_out, out_size);
}